// round 12
// baseline (speedup 1.0000x reference)
#include <cuda_runtime.h>
#include <cuda_bf16.h>
#include <cstdint>
#include <cstddef>

#define NKW   65536
#define NDOC  65536
#define EDGES 1048576
#define D     128
#define ASTRIDE 136   // bf16 elems per A smem row (272B, conflict-free)
#define WSTRIDE 72    // bf16 elems per W-half smem row (144B, conflict-free)

// ---------------- scratch (device-side only; never referenced from host) ----
__device__ float g_h0[(size_t)NKW * D];
__device__ int g_cntD[NDOC];
__device__ int g_cntK[NKW];
__device__ int g_bktD[(size_t)NDOC * 64];
__device__ int g_bktK[(size_t)NKW * 64];
// pre-tiled weights: [wslot][khalf][hi/lo][n*64 + kloc]; slots 0=W0 1=Wg1 2=Wg2 3=Wf2 4=Wt2
__device__ __nv_bfloat16 g_wt[5 * 2 * 2 * 8192];

// ---------------- init + weight pre-tiling (one launch) --------------------
__global__ void k_prep(const float* __restrict__ W0, const float* __restrict__ Wg1,
                       const float* __restrict__ Wg2, const float* __restrict__ Wf2,
                       const float* __restrict__ Wt2) {
    int idx = blockIdx.x * blockDim.x + threadIdx.x;
    if (idx < NDOC) g_cntD[idx] = 0;
    if (idx < NKW)  g_cntK[idx] = 0;
    if (idx >= 5 * 16384) return;
    int w = idx >> 14;
    int r = idx & 16383;
    int k = r >> 7, n = r & 127;
    const float* W = (w == 0) ? W0 : (w == 1) ? Wg1 : (w == 2) ? Wg2 : (w == 3) ? Wf2 : Wt2;
    float v = W[k * 128 + n];
    __nv_bfloat16 h = __float2bfloat16(v);
    size_t off = (size_t)w * 32768 + (size_t)(k >> 6) * 16384 + (size_t)n * 64 + (k & 63);
    g_wt[off] = h;
    g_wt[off + 8192] = __float2bfloat16(v - __bfloat162float(h));
}

// ---------------- graph build (bucketed, no scan) --------------------------
__global__ void k_fill_bkt(const int* __restrict__ src, const int* __restrict__ dst) {
    int i = blockIdx.x * blockDim.x + threadIdx.x;
    int s = src[i];
    int dl = dst[i] - NKW;
    int p = atomicAdd(&g_cntD[dl], 1);
    if (p < 64) g_bktD[(size_t)dl * 64 + p] = s;
    int q = atomicAdd(&g_cntK[s], 1);
    if (q < 64) g_bktK[(size_t)s * 64 + q] = dl;
}

// ---------------- mma.sync GEMM machinery ----------------------------------
// smem layout (bytes): A hi 34816 | A lo 34816 | W half hi 18432 | W half lo 18432
#define O_AH 0
#define O_AL 34816
#define O_WH 69632
#define SMEM_GEMM 106496
#define O_XS  106496
#define O_W1S 114688
#define SMEM_MLP 122880

__device__ __forceinline__ uint32_t smem_u32(const void* p) {
    uint32_t a;
    asm("{ .reg .u64 t; cvta.to.shared.u64 t, %1; cvt.u32.u64 %0, t; }" : "=r"(a) : "l"(p));
    return a;
}

#define CP_COMMIT asm volatile("cp.async.commit_group;" ::: "memory")
#define CP_WAIT(N) asm volatile("cp.async.wait_group %0;" :: "n"(N) : "memory")

__device__ __forceinline__ void cp16(uint32_t dst, const void* src) {
    asm volatile("cp.async.cg.shared.global [%0], [%1], 16;" :: "r"(dst), "l"(src) : "memory");
}

// stream one k-half of a pre-tiled weight (hi+lo, 32KB) into smem at dstb
__device__ __forceinline__ void stage_wt_half(uint32_t dstb, int wslot, int half, int tid) {
    const __nv_bfloat16* base = g_wt + (size_t)wslot * 32768 + (size_t)half * 16384;
#pragma unroll
    for (int it = 0; it < 8; it++) {
        int i = tid + it * 256;
        int hl = i >> 10;
        int idx = i & 1023;
        int n = idx >> 3;
        int c = idx & 7;
        cp16(dstb + hl * 18432 + n * 144 + c * 16, base + hl * 8192 + n * 64 + c * 8);
    }
}

__device__ __forceinline__ void mma16816(float* c, uint32_t a0, uint32_t a1, uint32_t a2, uint32_t a3,
                                         uint32_t b0, uint32_t b1) {
    asm volatile(
        "mma.sync.aligned.m16n8k16.row.col.f32.bf16.bf16.f32 "
        "{%0,%1,%2,%3}, {%4,%5,%6,%7}, {%8,%9}, {%0,%1,%2,%3};"
        : "+f"(c[0]), "+f"(c[1]), "+f"(c[2]), "+f"(c[3])
        : "r"(a0), "r"(a1), "r"(a2), "r"(a3), "r"(b0), "r"(b1));
}

__device__ __forceinline__ void zero_acc(float (&acc)[2][8][4]) {
#pragma unroll
    for (int i = 0; i < 2; i++)
#pragma unroll
        for (int j = 0; j < 8; j++)
#pragma unroll
            for (int q = 0; q < 4; q++) acc[i][j][q] = 0.f;
}

// acc += A(:, kk0..kk0+63) * Whalf^T, 3-split bf16; B fragments loaded per-j.
__device__ __forceinline__ void mma_gemm_half(const __nv_bfloat16* __restrict__ Ah,
                                              const __nv_bfloat16* __restrict__ Al,
                                              const __nv_bfloat16* __restrict__ Bh,
                                              const __nv_bfloat16* __restrict__ Bl,
                                              int kk0, float (&acc)[2][8][4], int wid, int lane) {
    int m0 = (wid & 3) * 32, n0 = (wid >> 2) * 64;
    int g = lane >> 2, t = lane & 3;
#pragma unroll
    for (int kk = 0; kk < 64; kk += 16) {
        uint32_t ah[2][4], al[2][4];
#pragma unroll
        for (int i = 0; i < 2; i++) {
            const __nv_bfloat16* b = &Ah[(m0 + i * 16 + g) * ASTRIDE + kk0 + kk + t * 2];
            ah[i][0] = *(const uint32_t*)b;
            ah[i][1] = *(const uint32_t*)(b + 8 * ASTRIDE);
            ah[i][2] = *(const uint32_t*)(b + 8);
            ah[i][3] = *(const uint32_t*)(b + 8 * ASTRIDE + 8);
            const __nv_bfloat16* bl2 = &Al[(m0 + i * 16 + g) * ASTRIDE + kk0 + kk + t * 2];
            al[i][0] = *(const uint32_t*)bl2;
            al[i][1] = *(const uint32_t*)(bl2 + 8 * ASTRIDE);
            al[i][2] = *(const uint32_t*)(bl2 + 8);
            al[i][3] = *(const uint32_t*)(bl2 + 8 * ASTRIDE + 8);
        }
#pragma unroll
        for (int j = 0; j < 8; j++) {
            const __nv_bfloat16* b = &Bh[(n0 + j * 8 + g) * WSTRIDE + kk + t * 2];
            uint32_t bh0 = *(const uint32_t*)b;
            uint32_t bh1 = *(const uint32_t*)(b + 8);
            const __nv_bfloat16* b2 = &Bl[(n0 + j * 8 + g) * WSTRIDE + kk + t * 2];
            uint32_t bl0 = *(const uint32_t*)b2;
            uint32_t bl1 = *(const uint32_t*)(b2 + 8);
#pragma unroll
            for (int i = 0; i < 2; i++) {
                mma16816(acc[i][j], ah[i][0], ah[i][1], ah[i][2], ah[i][3], bh0, bh1);
                mma16816(acc[i][j], ah[i][0], ah[i][1], ah[i][2], ah[i][3], bl0, bl1);
                mma16816(acc[i][j], al[i][0], al[i][1], al[i][2], al[i][3], bh0, bh1);
            }
        }
    }
}

__device__ __forceinline__ void split_pair(float v0, float v1, __nv_bfloat162* hp, __nv_bfloat162* lp) {
    __nv_bfloat16 h0 = __float2bfloat16(v0), h1 = __float2bfloat16(v1);
    hp->x = h0; hp->y = h1;
    lp->x = __float2bfloat16(v0 - __bfloat162float(h0));
    lp->y = __float2bfloat16(v1 - __bfloat162float(h1));
}

// fp32 rows -> bf16 hi/lo A tiles (float4 loads, 8B packed stores)
__device__ __forceinline__ void conv_rows(const float* __restrict__ src, char* sm, int tid) {
    __nv_bfloat16* Ah = (__nv_bfloat16*)(sm + O_AH);
    __nv_bfloat16* Al = (__nv_bfloat16*)(sm + O_AL);
    for (int i = tid; i < 4096; i += 256) {
        int row = i >> 5, c = (i & 31) * 4;
        float4 v = *(const float4*)(src + (size_t)row * 128 + c);
        __nv_bfloat162 hp0, lp0, hp1, lp1;
        split_pair(v.x, v.y, &hp0, &lp0);
        split_pair(v.z, v.w, &hp1, &lp1);
        __nv_bfloat162* ph = (__nv_bfloat162*)&Ah[row * ASTRIDE + c];
        ph[0] = hp0; ph[1] = hp1;
        __nv_bfloat162* pl = (__nv_bfloat162*)&Al[row * ASTRIDE + c];
        pl[0] = lp0; pl[1] = lp1;
    }
}

// shared epilogue: dst = relu(acc + bias) for 128-row tile
__device__ __forceinline__ void epi_relu(float* __restrict__ dst, int row0, const float* __restrict__ bias,
                                         float (&acc)[2][8][4], int wid, int lane) {
    int m0 = (wid & 3) * 32, n0 = (wid >> 2) * 64;
    int g = lane >> 2, t = lane & 3;
#pragma unroll
    for (int i = 0; i < 2; i++)
#pragma unroll
        for (int j = 0; j < 8; j++) {
            int row = m0 + i * 16 + g, col = n0 + j * 8 + t * 2;
            float ba = __ldg(&bias[col]), bb = __ldg(&bias[col + 1]);
            *(float2*)&dst[(size_t)(row0 + row) * 128 + col] =
                make_float2(fmaxf(acc[i][j][0] + ba, 0.f), fmaxf(acc[i][j][1] + bb, 0.f));
            *(float2*)&dst[(size_t)(row0 + row + 8) * 128 + col] =
                make_float2(fmaxf(acc[i][j][2] + ba, 0.f), fmaxf(acc[i][j][3] + bb, 0.f));
        }
}

// ------------- layer 0 GEMM: g_h0 = relu(X W0 + b0) -------------------------
__global__ void __launch_bounds__(256, 2)
k_gemm0(const float* __restrict__ X, const float* __restrict__ bias, int wslot) {
    extern __shared__ char sm[];
    uint32_t sb = smem_u32(sm);
    int tid = threadIdx.x, wid = tid >> 5, lane = tid & 31;
    int row0 = blockIdx.x * 128;
    const __nv_bfloat16* Ah = (const __nv_bfloat16*)(sm + O_AH);
    const __nv_bfloat16* Al = (const __nv_bfloat16*)(sm + O_AL);
    const __nv_bfloat16* Wh = (const __nv_bfloat16*)(sm + O_WH);
    const __nv_bfloat16* Wl = (const __nv_bfloat16*)(sm + O_WH + 18432);

    stage_wt_half(sb + O_WH, wslot, 0, tid);
    CP_COMMIT;
    conv_rows(X + (size_t)row0 * 128, sm, tid);
    CP_WAIT(0);
    __syncthreads();

    float acc[2][8][4];
    zero_acc(acc);
    mma_gemm_half(Ah, Al, Wh, Wl, 0, acc, wid, lane);
    __syncthreads();
    stage_wt_half(sb + O_WH, wslot, 1, tid);
    CP_COMMIT;
    CP_WAIT(0);
    __syncthreads();
    mma_gemm_half(Ah, Al, Wh, Wl, 64, acc, wid, lane);
    epi_relu(g_h0, row0, bias, acc, wid, lane);
}

// ------------- fused gather + GEMM layers ------------------------------------
__device__ __forceinline__ void acc_add(float4& a, const float4& v) {
    a.x += v.x; a.y += v.y; a.z += v.z; a.w += v.w;
}

// L=1: A row = rsqrt(deg_d)*sum_{kw in N(d)} h0[kw]             (docx pre-GEMM)
// L=2: A row = rsqrt(deg_k)*sum_{d in N(k)} docx[d] + h0[k]/deg (kw pre-GEMM)
template <int L>
__global__ void __launch_bounds__(256, 2)
k_lgemm(const float* __restrict__ docx, const float* __restrict__ bias,
        float* __restrict__ dst, int wslot) {
    extern __shared__ char sm[];
    uint32_t sb = smem_u32(sm);
    int tid = threadIdx.x, wid = tid >> 5, lane = tid & 31;
    int row0 = blockIdx.x * 128;
    __nv_bfloat16* Ah = (__nv_bfloat16*)(sm + O_AH);
    __nv_bfloat16* Al = (__nv_bfloat16*)(sm + O_AL);
    const __nv_bfloat16* Wh = (const __nv_bfloat16*)(sm + O_WH);
    const __nv_bfloat16* Wl = (const __nv_bfloat16*)(sm + O_WH + 18432);

    stage_wt_half(sb + O_WH, wslot, 0, tid);   // overlaps the gather below
    CP_COMMIT;

    // gather phase: each warp builds 16 A-tile rows
    const float* S = (L == 1) ? g_h0 : docx;
    for (int r = 0; r < 16; r++) {
        int wr = wid * 16 + r;
        int node = row0 + wr;
        int n = min((L == 1) ? g_cntD[node] : g_cntK[node], 64);
        const int* bkt = ((L == 1) ? g_bktD : g_bktK) + (size_t)node * 64;
        int m1 = bkt[lane];
        int m2 = bkt[32 + lane];
        float4 a0 = make_float4(0.f, 0.f, 0.f, 0.f), a1 = a0;
        int n1 = n < 32 ? n : 32;
        int e = 0;
        for (; e + 4 <= n1; e += 4) {
            int i0 = __shfl_sync(0xFFFFFFFFu, m1, e);
            int i1 = __shfl_sync(0xFFFFFFFFu, m1, e + 1);
            int i2 = __shfl_sync(0xFFFFFFFFu, m1, e + 2);
            int i3 = __shfl_sync(0xFFFFFFFFu, m1, e + 3);
            float4 v0 = *(const float4*)&S[(size_t)i0 * D + lane * 4];
            float4 v1 = *(const float4*)&S[(size_t)i1 * D + lane * 4];
            float4 v2 = *(const float4*)&S[(size_t)i2 * D + lane * 4];
            float4 v3 = *(const float4*)&S[(size_t)i3 * D + lane * 4];
            acc_add(a0, v0); acc_add(a1, v1); acc_add(a0, v2); acc_add(a1, v3);
        }
        for (; e < n1; e++) {
            int i0 = __shfl_sync(0xFFFFFFFFu, m1, e);
            float4 v = *(const float4*)&S[(size_t)i0 * D + lane * 4];
            acc_add(a0, v);
        }
        for (e = 32; e < n; e++) {
            int i0 = __shfl_sync(0xFFFFFFFFu, m2, e - 32);
            float4 v = *(const float4*)&S[(size_t)i0 * D + lane * 4];
            acc_add(a1, v);
        }
        float deg = (float)(n + 1);
        float s = rsqrtf(deg);
        float4 v;
        v.x = (a0.x + a1.x) * s;
        v.y = (a0.y + a1.y) * s;
        v.z = (a0.z + a1.z) * s;
        v.w = (a0.w + a1.w) * s;
        if (L == 2) {
            float inv = 1.f / deg;
            float4 hk = *(const float4*)&g_h0[(size_t)node * D + lane * 4];
            v.x += hk.x * inv; v.y += hk.y * inv; v.z += hk.z * inv; v.w += hk.w * inv;
        }
        __nv_bfloat162 hp0, lp0, hp1, lp1;
        split_pair(v.x, v.y, &hp0, &lp0);
        split_pair(v.z, v.w, &hp1, &lp1);
        int c = lane * 4;
        __nv_bfloat162* ph = (__nv_bfloat162*)&Ah[wr * ASTRIDE + c];
        ph[0] = hp0; ph[1] = hp1;
        __nv_bfloat162* pl = (__nv_bfloat162*)&Al[wr * ASTRIDE + c];
        pl[0] = lp0; pl[1] = lp1;
    }
    CP_WAIT(0);
    __syncthreads();

    float acc[2][8][4];
    zero_acc(acc);
    mma_gemm_half(Ah, Al, Wh, Wl, 0, acc, wid, lane);
    __syncthreads();
    stage_wt_half(sb + O_WH, wslot, 1, tid);
    CP_COMMIT;
    CP_WAIT(0);
    __syncthreads();
    mma_gemm_half(Ah, Al, Wh, Wl, 64, acc, wid, lane);
    epi_relu(dst, row0, bias, acc, wid, lane);
}

// ------------- fused feedback+time MLP, single RMW --------------------------
template <int KIN>
__device__ __forceinline__ void buildH(char* sm, const float* __restrict__ b1, int tid) {
    const float* XS = (const float*)(sm + O_XS);
    const float* W1 = (const float*)(sm + O_W1S);
    __nv_bfloat16* Ah = (__nv_bfloat16*)(sm + O_AH);
    __nv_bfloat16* Al = (__nv_bfloat16*)(sm + O_AL);
    for (int i = tid; i < 8192; i += 256) {
        int row = i >> 6, c = (i & 63) * 2;
        float a0 = __ldg(&b1[c]), a1 = __ldg(&b1[c + 1]);
#pragma unroll
        for (int k = 0; k < KIN; k++) {
            float x = XS[row * KIN + k];
            a0 = fmaf(x, W1[k * 128 + c], a0);
            a1 = fmaf(x, W1[k * 128 + c + 1], a1);
        }
        __nv_bfloat162 hp, lp;
        split_pair(fmaxf(a0, 0.f), fmaxf(a1, 0.f), &hp, &lp);
        *(__nv_bfloat162*)&Ah[row * ASTRIDE + c] = hp;
        *(__nv_bfloat162*)&Al[row * ASTRIDE + c] = lp;
    }
}

template <int KIN>
__device__ __forceinline__ void mlp_side(char* sm, uint32_t sb,
                                         const float* __restrict__ Xin,
                                         const float* __restrict__ W1,
                                         const float* __restrict__ b1,
                                         int wslot, float (&acc)[2][8][4],
                                         int tid, int wid, int lane, int row0) {
    const __nv_bfloat16* Ah = (const __nv_bfloat16*)(sm + O_AH);
    const __nv_bfloat16* Al = (const __nv_bfloat16*)(sm + O_AL);
    const __nv_bfloat16* Wh = (const __nv_bfloat16*)(sm + O_WH);
    const __nv_bfloat16* Wl = (const __nv_bfloat16*)(sm + O_WH + 18432);

    stage_wt_half(sb + O_WH, wslot, 0, tid);
    CP_COMMIT;
    for (int i = tid; i < 32 * KIN; i += 256)
        ((float4*)(sm + O_XS))[i] = ((const float4*)(Xin + (size_t)row0 * KIN))[i];
    for (int i = tid; i < 32 * KIN; i += 256)
        ((float4*)(sm + O_W1S))[i] = ((const float4*)W1)[i];
    __syncthreads();
    buildH<KIN>(sm, b1, tid);
    CP_WAIT(0);
    __syncthreads();
    zero_acc(acc);
    mma_gemm_half(Ah, Al, Wh, Wl, 0, acc, wid, lane);
    __syncthreads();
    stage_wt_half(sb + O_WH, wslot, 1, tid);
    CP_COMMIT;
    CP_WAIT(0);
    __syncthreads();
    mma_gemm_half(Ah, Al, Wh, Wl, 64, acc, wid, lane);
    __syncthreads();
}

__global__ void __launch_bounds__(256)
k_mlp_fused(const float* __restrict__ Xf, const float* __restrict__ Wf1, const float* __restrict__ bf1,
            const float* __restrict__ bf2,
            const float* __restrict__ Xt, const float* __restrict__ Wt1, const float* __restrict__ bt1,
            const float* __restrict__ bt2,
            float* __restrict__ outdoc) {
    extern __shared__ char sm[];
    uint32_t sb = smem_u32(sm);
    int tid = threadIdx.x, wid = tid >> 5, lane = tid & 31;
    int row0 = blockIdx.x * 128;

    float accF[2][8][4], accT[2][8][4];
    mlp_side<16>(sm, sb, Xf, Wf1, bf1, 3, accF, tid, wid, lane, row0);
    mlp_side<8>(sm, sb, Xt, Wt1, bt1, 4, accT, tid, wid, lane, row0);

    int m0 = (wid & 3) * 32, n0 = (wid >> 2) * 64;
    int g = lane >> 2, t = lane & 3;
#pragma unroll
    for (int i = 0; i < 2; i++)
#pragma unroll
        for (int j = 0; j < 8; j++) {
            int row = m0 + i * 16 + g, col = n0 + j * 8 + t * 2;
            float fa = __ldg(&bf2[col]), fb = __ldg(&bf2[col + 1]);
            float ta = __ldg(&bt2[col]), tb = __ldg(&bt2[col + 1]);
            float2* p = (float2*)&outdoc[(size_t)(row0 + row) * 128 + col];
            float2 o = *p;
            o.x *= (accF[i][j][0] + fa) * (accT[i][j][0] + ta);
            o.y *= (accF[i][j][1] + fb) * (accT[i][j][1] + tb);
            *p = o;
            p = (float2*)&outdoc[(size_t)(row0 + row + 8) * 128 + col];
            o = *p;
            o.x *= (accF[i][j][2] + fa) * (accT[i][j][2] + ta);
            o.y *= (accF[i][j][3] + fb) * (accT[i][j][3] + tb);
            *p = o;
        }
}

// ---------------- launch ----------------------------------------------------
extern "C" void kernel_launch(void* const* d_in, const int* in_sizes, int n_in,
                              void* d_out, int out_size) {
    const float* X   = (const float*)d_in[0];
    const float* Xfb = (const float*)d_in[1];
    const float* Xt  = (const float*)d_in[2];
    const int* e_kw2doc = (const int*)d_in[3];
    const float* W0  = (const float*)d_in[6];
    const float* b0  = (const float*)d_in[7];
    const float* Wg1 = (const float*)d_in[8];
    const float* bg1 = (const float*)d_in[9];
    const float* Wg2 = (const float*)d_in[10];
    const float* bg2 = (const float*)d_in[11];
    const float* Wf1 = (const float*)d_in[12];
    const float* bf1 = (const float*)d_in[13];
    const float* Wf2 = (const float*)d_in[14];
    const float* bf2 = (const float*)d_in[15];
    const float* Wt1 = (const float*)d_in[16];
    const float* bt1 = (const float*)d_in[17];
    const float* Wt2 = (const float*)d_in[18];
    const float* bt2 = (const float*)d_in[19];
    float* out = (float*)d_out;
    float* outdoc = out + (size_t)NKW * D;
    const int* src = e_kw2doc;
    const int* dst = e_kw2doc + EDGES;

    cudaFuncSetAttribute(k_gemm0, cudaFuncAttributeMaxDynamicSharedMemorySize, SMEM_GEMM);
    cudaFuncSetAttribute(k_lgemm<1>, cudaFuncAttributeMaxDynamicSharedMemorySize, SMEM_GEMM);
    cudaFuncSetAttribute(k_lgemm<2>, cudaFuncAttributeMaxDynamicSharedMemorySize, SMEM_GEMM);
    cudaFuncSetAttribute(k_mlp_fused, cudaFuncAttributeMaxDynamicSharedMemorySize, SMEM_MLP);

    // init counters + weight pre-tiling, then bucketed adjacency build
    k_prep<<<320, 256>>>(W0, Wg1, Wg2, Wf2, Wt2);
    k_fill_bkt<<<EDGES / 256, 256>>>(src, dst);

    // layer 0: h0 = relu(X W0 + b0) -> g_h0
    k_gemm0<<<NKW / 128, 256, SMEM_GEMM>>>(X, b0, 0);

    // layer 1 (fused gather+GEMM): docx = relu(norm-agg(h0) Wg1 + bg1) -> doc rows of out
    k_lgemm<1><<<NDOC / 128, 256, SMEM_GEMM>>>(nullptr, bg1, outdoc, 1);

    // layer 2 (fused gather+GEMM): kwx = relu((norm-agg(docx)+self) Wg2 + bg2) -> kw rows
    k_lgemm<2><<<NKW / 128, 256, SMEM_GEMM>>>(outdoc, bg2, out, 2);

    // feedback + time MLPs multiplied into doc rows (single RMW)
    k_mlp_fused<<<NDOC / 128, 256, SMEM_MLP>>>(Xfb, Wf1, bf1, bf2,
                                               Xt, Wt1, bt1, bt2, outdoc);
}

// round 13
// speedup vs baseline: 1.0835x; 1.0835x over previous
#include <cuda_runtime.h>
#include <cuda_bf16.h>
#include <cstdint>
#include <cstddef>

#define NKW   65536
#define NDOC  65536
#define EDGES 1048576
#define D     128
#define ASTRIDE 136   // bf16 elems per A smem row (272B, conflict-free)
#define WSTRIDE 72    // bf16 elems per W-half smem row (144B, conflict-free)

// ---------------- scratch (device-side only; never referenced from host) ----
__device__ float g_h0[(size_t)NKW * D];
__device__ float g_agg[(size_t)NDOC * D];
__device__ int g_cntD[NDOC];
__device__ int g_cntK[NKW];
__device__ int g_bktD[(size_t)NDOC * 64];
__device__ int g_bktK[(size_t)NKW * 64];
// pre-tiled weights: [wslot][khalf][hi/lo][n*64 + kloc]; slots 0=W0 1=Wg1 2=Wg2 3=Wf2 4=Wt2
__device__ __nv_bfloat16 g_wt[5 * 2 * 2 * 8192];

// ---------------- init + weight pre-tiling (one launch) --------------------
__global__ void k_prep(const float* __restrict__ W0, const float* __restrict__ Wg1,
                       const float* __restrict__ Wg2, const float* __restrict__ Wf2,
                       const float* __restrict__ Wt2) {
    int idx = blockIdx.x * blockDim.x + threadIdx.x;
    if (idx < NDOC) g_cntD[idx] = 0;
    if (idx < NKW)  g_cntK[idx] = 0;
    if (idx >= 5 * 16384) return;
    int w = idx >> 14;
    int r = idx & 16383;
    int k = r >> 7, n = r & 127;
    const float* W = (w == 0) ? W0 : (w == 1) ? Wg1 : (w == 2) ? Wg2 : (w == 3) ? Wf2 : Wt2;
    float v = W[k * 128 + n];
    __nv_bfloat16 h = __float2bfloat16(v);
    size_t off = (size_t)w * 32768 + (size_t)(k >> 6) * 16384 + (size_t)n * 64 + (k & 63);
    g_wt[off] = h;
    g_wt[off + 8192] = __float2bfloat16(v - __bfloat162float(h));
}

// ---------------- graph build (bucketed, no scan) --------------------------
__global__ void k_fill_bkt(const int* __restrict__ src, const int* __restrict__ dst) {
    int i = blockIdx.x * blockDim.x + threadIdx.x;
    int s = src[i];
    int dl = dst[i] - NKW;
    int p = atomicAdd(&g_cntD[dl], 1);
    if (p < 64) g_bktD[(size_t)dl * 64 + p] = s;
    int q = atomicAdd(&g_cntK[s], 1);
    if (q < 64) g_bktK[(size_t)s * 64 + q] = dl;
}

// ---------------- mma.sync GEMM machinery ----------------------------------
// smem layout (bytes): A hi 34816 | A lo 34816 | W half hi 18432 | W half lo 18432
#define O_AH 0
#define O_AL 34816
#define O_WH 69632
#define SMEM_GEMM 106496
#define O_XS  106496
#define O_W1S 114688
#define SMEM_MLP 122880

__device__ __forceinline__ uint32_t smem_u32(const void* p) {
    uint32_t a;
    asm("{ .reg .u64 t; cvta.to.shared.u64 t, %1; cvt.u32.u64 %0, t; }" : "=r"(a) : "l"(p));
    return a;
}

#define CP_COMMIT asm volatile("cp.async.commit_group;" ::: "memory")
#define CP_WAIT(N) asm volatile("cp.async.wait_group %0;" :: "n"(N) : "memory")

__device__ __forceinline__ void cp16(uint32_t dst, const void* src) {
    asm volatile("cp.async.cg.shared.global [%0], [%1], 16;" :: "r"(dst), "l"(src) : "memory");
}

// stream one k-half of a pre-tiled weight (hi+lo, 32KB) into smem at dstb
__device__ __forceinline__ void stage_wt_half(uint32_t dstb, int wslot, int half, int tid) {
    const __nv_bfloat16* base = g_wt + (size_t)wslot * 32768 + (size_t)half * 16384;
#pragma unroll
    for (int it = 0; it < 8; it++) {
        int i = tid + it * 256;
        int hl = i >> 10;
        int idx = i & 1023;
        int n = idx >> 3;
        int c = idx & 7;
        cp16(dstb + hl * 18432 + n * 144 + c * 16, base + hl * 8192 + n * 64 + c * 8);
    }
}

__device__ __forceinline__ void mma16816(float* c, uint32_t a0, uint32_t a1, uint32_t a2, uint32_t a3,
                                         uint32_t b0, uint32_t b1) {
    asm volatile(
        "mma.sync.aligned.m16n8k16.row.col.f32.bf16.bf16.f32 "
        "{%0,%1,%2,%3}, {%4,%5,%6,%7}, {%8,%9}, {%0,%1,%2,%3};"
        : "+f"(c[0]), "+f"(c[1]), "+f"(c[2]), "+f"(c[3])
        : "r"(a0), "r"(a1), "r"(a2), "r"(a3), "r"(b0), "r"(b1));
}

__device__ __forceinline__ void zero_acc(float (&acc)[2][8][4]) {
#pragma unroll
    for (int i = 0; i < 2; i++)
#pragma unroll
        for (int j = 0; j < 8; j++)
#pragma unroll
            for (int q = 0; q < 4; q++) acc[i][j][q] = 0.f;
}

// acc += A(:, kk0..kk0+63) * Whalf^T, 3-split bf16; B fragments loaded per-j.
__device__ __forceinline__ void mma_gemm_half(const __nv_bfloat16* __restrict__ Ah,
                                              const __nv_bfloat16* __restrict__ Al,
                                              const __nv_bfloat16* __restrict__ Bh,
                                              const __nv_bfloat16* __restrict__ Bl,
                                              int kk0, float (&acc)[2][8][4], int wid, int lane) {
    int m0 = (wid & 3) * 32, n0 = (wid >> 2) * 64;
    int g = lane >> 2, t = lane & 3;
#pragma unroll
    for (int kk = 0; kk < 64; kk += 16) {
        uint32_t ah[2][4], al[2][4];
#pragma unroll
        for (int i = 0; i < 2; i++) {
            const __nv_bfloat16* b = &Ah[(m0 + i * 16 + g) * ASTRIDE + kk0 + kk + t * 2];
            ah[i][0] = *(const uint32_t*)b;
            ah[i][1] = *(const uint32_t*)(b + 8 * ASTRIDE);
            ah[i][2] = *(const uint32_t*)(b + 8);
            ah[i][3] = *(const uint32_t*)(b + 8 * ASTRIDE + 8);
            const __nv_bfloat16* bl2 = &Al[(m0 + i * 16 + g) * ASTRIDE + kk0 + kk + t * 2];
            al[i][0] = *(const uint32_t*)bl2;
            al[i][1] = *(const uint32_t*)(bl2 + 8 * ASTRIDE);
            al[i][2] = *(const uint32_t*)(bl2 + 8);
            al[i][3] = *(const uint32_t*)(bl2 + 8 * ASTRIDE + 8);
        }
#pragma unroll
        for (int j = 0; j < 8; j++) {
            const __nv_bfloat16* b = &Bh[(n0 + j * 8 + g) * WSTRIDE + kk + t * 2];
            uint32_t bh0 = *(const uint32_t*)b;
            uint32_t bh1 = *(const uint32_t*)(b + 8);
            const __nv_bfloat16* b2 = &Bl[(n0 + j * 8 + g) * WSTRIDE + kk + t * 2];
            uint32_t bl0 = *(const uint32_t*)b2;
            uint32_t bl1 = *(const uint32_t*)(b2 + 8);
#pragma unroll
            for (int i = 0; i < 2; i++) {
                mma16816(acc[i][j], ah[i][0], ah[i][1], ah[i][2], ah[i][3], bh0, bh1);
                mma16816(acc[i][j], ah[i][0], ah[i][1], ah[i][2], ah[i][3], bl0, bl1);
                mma16816(acc[i][j], al[i][0], al[i][1], al[i][2], al[i][3], bh0, bh1);
            }
        }
    }
}

__device__ __forceinline__ void split_pair(float v0, float v1, __nv_bfloat162* hp, __nv_bfloat162* lp) {
    __nv_bfloat16 h0 = __float2bfloat16(v0), h1 = __float2bfloat16(v1);
    hp->x = h0; hp->y = h1;
    lp->x = __float2bfloat16(v0 - __bfloat162float(h0));
    lp->y = __float2bfloat16(v1 - __bfloat162float(h1));
}

// fp32 rows -> bf16 hi/lo A tiles (float4 loads, 8B packed stores)
__device__ __forceinline__ void conv_rows(const float* __restrict__ src, char* sm, int tid) {
    __nv_bfloat16* Ah = (__nv_bfloat16*)(sm + O_AH);
    __nv_bfloat16* Al = (__nv_bfloat16*)(sm + O_AL);
    for (int i = tid; i < 4096; i += 256) {
        int row = i >> 5, c = (i & 31) * 4;
        float4 v = *(const float4*)(src + (size_t)row * 128 + c);
        __nv_bfloat162 hp0, lp0, hp1, lp1;
        split_pair(v.x, v.y, &hp0, &lp0);
        split_pair(v.z, v.w, &hp1, &lp1);
        __nv_bfloat162* ph = (__nv_bfloat162*)&Ah[row * ASTRIDE + c];
        ph[0] = hp0; ph[1] = hp1;
        __nv_bfloat162* pl = (__nv_bfloat162*)&Al[row * ASTRIDE + c];
        pl[0] = lp0; pl[1] = lp1;
    }
}

// ------------- unified single-GEMM kernel: dst = relu(A @ Wt[wslot] + bias) --
// SRC: 0 = external pointer, 1 = g_agg.  DST: 0 = external pointer, 1 = g_h0.
template <int SRC, int DST>
__global__ void __launch_bounds__(256, 2)
k_gemm_one(const float* __restrict__ Aext, const float* __restrict__ bias,
           float* __restrict__ dstext, int wslot) {
    extern __shared__ char sm[];
    uint32_t sb = smem_u32(sm);
    int tid = threadIdx.x, wid = tid >> 5, lane = tid & 31;
    int row0 = blockIdx.x * 128;
    const float* A = (SRC == 1) ? g_agg : Aext;
    float* dst = (DST == 1) ? g_h0 : dstext;
    const __nv_bfloat16* Ah = (const __nv_bfloat16*)(sm + O_AH);
    const __nv_bfloat16* Al = (const __nv_bfloat16*)(sm + O_AL);
    const __nv_bfloat16* Wh = (const __nv_bfloat16*)(sm + O_WH);
    const __nv_bfloat16* Wl = (const __nv_bfloat16*)(sm + O_WH + 18432);

    stage_wt_half(sb + O_WH, wslot, 0, tid);
    CP_COMMIT;
    conv_rows(A + (size_t)row0 * 128, sm, tid);
    CP_WAIT(0);
    __syncthreads();

    float acc[2][8][4];
    zero_acc(acc);
    mma_gemm_half(Ah, Al, Wh, Wl, 0, acc, wid, lane);
    __syncthreads();
    stage_wt_half(sb + O_WH, wslot, 1, tid);
    CP_COMMIT;
    CP_WAIT(0);
    __syncthreads();
    mma_gemm_half(Ah, Al, Wh, Wl, 64, acc, wid, lane);

    int m0 = (wid & 3) * 32, n0 = (wid >> 2) * 64;
    int g = lane >> 2, t = lane & 3;
#pragma unroll
    for (int i = 0; i < 2; i++)
#pragma unroll
        for (int j = 0; j < 8; j++) {
            int row = m0 + i * 16 + g, col = n0 + j * 8 + t * 2;
            float ba = __ldg(&bias[col]), bb = __ldg(&bias[col + 1]);
            *(float2*)&dst[(size_t)(row0 + row) * 128 + col] =
                make_float2(fmaxf(acc[i][j][0] + ba, 0.f), fmaxf(acc[i][j][1] + bb, 0.f));
            *(float2*)&dst[(size_t)(row0 + row + 8) * 128 + col] =
                make_float2(fmaxf(acc[i][j][2] + ba, 0.f), fmaxf(acc[i][j][3] + bb, 0.f));
        }
}

// ------------- gathers (unroll 8, MLP>=8) ------------------------------------
__device__ __forceinline__ void acc_add(float4& a, const float4& v) {
    a.x += v.x; a.y += v.y; a.z += v.z; a.w += v.w;
}

// shared gather core: returns (a0+a1) over bucket neighbors of `node`
__device__ __forceinline__ float4 gather_core(const float* __restrict__ S,
                                              const int* __restrict__ bkt,
                                              int n, int lane) {
    int m1 = bkt[lane];
    int m2 = bkt[32 + lane];
    float4 a0 = make_float4(0.f, 0.f, 0.f, 0.f), a1 = a0;
    int n1 = n < 32 ? n : 32;
    int e = 0;
    for (; e + 8 <= n1; e += 8) {
        int i0 = __shfl_sync(0xFFFFFFFFu, m1, e);
        int i1 = __shfl_sync(0xFFFFFFFFu, m1, e + 1);
        int i2 = __shfl_sync(0xFFFFFFFFu, m1, e + 2);
        int i3 = __shfl_sync(0xFFFFFFFFu, m1, e + 3);
        int i4 = __shfl_sync(0xFFFFFFFFu, m1, e + 4);
        int i5 = __shfl_sync(0xFFFFFFFFu, m1, e + 5);
        int i6 = __shfl_sync(0xFFFFFFFFu, m1, e + 6);
        int i7 = __shfl_sync(0xFFFFFFFFu, m1, e + 7);
        float4 v0 = *(const float4*)&S[(size_t)i0 * D + lane * 4];
        float4 v1 = *(const float4*)&S[(size_t)i1 * D + lane * 4];
        float4 v2 = *(const float4*)&S[(size_t)i2 * D + lane * 4];
        float4 v3 = *(const float4*)&S[(size_t)i3 * D + lane * 4];
        float4 v4 = *(const float4*)&S[(size_t)i4 * D + lane * 4];
        float4 v5 = *(const float4*)&S[(size_t)i5 * D + lane * 4];
        float4 v6 = *(const float4*)&S[(size_t)i6 * D + lane * 4];
        float4 v7 = *(const float4*)&S[(size_t)i7 * D + lane * 4];
        acc_add(a0, v0); acc_add(a1, v1); acc_add(a0, v2); acc_add(a1, v3);
        acc_add(a0, v4); acc_add(a1, v5); acc_add(a0, v6); acc_add(a1, v7);
    }
    for (; e + 4 <= n1; e += 4) {
        int i0 = __shfl_sync(0xFFFFFFFFu, m1, e);
        int i1 = __shfl_sync(0xFFFFFFFFu, m1, e + 1);
        int i2 = __shfl_sync(0xFFFFFFFFu, m1, e + 2);
        int i3 = __shfl_sync(0xFFFFFFFFu, m1, e + 3);
        float4 v0 = *(const float4*)&S[(size_t)i0 * D + lane * 4];
        float4 v1 = *(const float4*)&S[(size_t)i1 * D + lane * 4];
        float4 v2 = *(const float4*)&S[(size_t)i2 * D + lane * 4];
        float4 v3 = *(const float4*)&S[(size_t)i3 * D + lane * 4];
        acc_add(a0, v0); acc_add(a1, v1); acc_add(a0, v2); acc_add(a1, v3);
    }
    for (; e < n1; e++) {
        int i0 = __shfl_sync(0xFFFFFFFFu, m1, e);
        float4 v = *(const float4*)&S[(size_t)i0 * D + lane * 4];
        acc_add(a0, v);
    }
    for (e = 32; e + 4 <= n; e += 4) {
        int i0 = __shfl_sync(0xFFFFFFFFu, m2, e - 32);
        int i1 = __shfl_sync(0xFFFFFFFFu, m2, e - 31);
        int i2 = __shfl_sync(0xFFFFFFFFu, m2, e - 30);
        int i3 = __shfl_sync(0xFFFFFFFFu, m2, e - 29);
        float4 v0 = *(const float4*)&S[(size_t)i0 * D + lane * 4];
        float4 v1 = *(const float4*)&S[(size_t)i1 * D + lane * 4];
        float4 v2 = *(const float4*)&S[(size_t)i2 * D + lane * 4];
        float4 v3 = *(const float4*)&S[(size_t)i3 * D + lane * 4];
        acc_add(a0, v0); acc_add(a1, v1); acc_add(a0, v2); acc_add(a1, v3);
    }
    for (; e < n; e++) {
        int i0 = __shfl_sync(0xFFFFFFFFu, m2, e - 32);
        float4 v = *(const float4*)&S[(size_t)i0 * D + lane * 4];
        acc_add(a1, v);
    }
    float4 r;
    r.x = a0.x + a1.x; r.y = a0.y + a1.y; r.z = a0.z + a1.z; r.w = a0.w + a1.w;
    return r;
}

// g_agg[d] = rsqrt(deg_d) * sum h0[kw]
__global__ void k_gather1() {
    int w = (blockIdx.x * blockDim.x + threadIdx.x) >> 5;
    int lane = threadIdx.x & 31;
    if (w >= NDOC) return;
    int n = min(g_cntD[w], 64);
    float4 r = gather_core(g_h0, &g_bktD[(size_t)w * 64], n, lane);
    float s = rsqrtf((float)(n + 1));
    r.x *= s; r.y *= s; r.z *= s; r.w *= s;
    *(float4*)&g_agg[(size_t)w * D + lane * 4] = r;
}

// g_agg[k] = rsqrt(deg_k) * sum docx[dl] + h0[k] / deg_k
__global__ void k_gather2(const float* __restrict__ docx) {
    int k = (blockIdx.x * blockDim.x + threadIdx.x) >> 5;
    int lane = threadIdx.x & 31;
    if (k >= NKW) return;
    int n = min(g_cntK[k], 64);
    float4 r = gather_core(docx, &g_bktK[(size_t)k * 64], n, lane);
    float deg = (float)(n + 1);
    float s = rsqrtf(deg);
    float inv = 1.f / deg;
    float4 hk = *(const float4*)&g_h0[(size_t)k * D + lane * 4];
    r.x = r.x * s + hk.x * inv;
    r.y = r.y * s + hk.y * inv;
    r.z = r.z * s + hk.z * inv;
    r.w = r.w * s + hk.w * inv;
    *(float4*)&g_agg[(size_t)k * D + lane * 4] = r;
}

// ------------- fused feedback+time MLP, single RMW --------------------------
template <int KIN>
__device__ __forceinline__ void buildH(char* sm, const float* __restrict__ b1, int tid) {
    const float* XS = (const float*)(sm + O_XS);
    const float* W1 = (const float*)(sm + O_W1S);
    __nv_bfloat16* Ah = (__nv_bfloat16*)(sm + O_AH);
    __nv_bfloat16* Al = (__nv_bfloat16*)(sm + O_AL);
    for (int i = tid; i < 8192; i += 256) {
        int row = i >> 6, c = (i & 63) * 2;
        float a0 = __ldg(&b1[c]), a1 = __ldg(&b1[c + 1]);
#pragma unroll
        for (int k = 0; k < KIN; k++) {
            float x = XS[row * KIN + k];
            a0 = fmaf(x, W1[k * 128 + c], a0);
            a1 = fmaf(x, W1[k * 128 + c + 1], a1);
        }
        __nv_bfloat162 hp, lp;
        split_pair(fmaxf(a0, 0.f), fmaxf(a1, 0.f), &hp, &lp);
        *(__nv_bfloat162*)&Ah[row * ASTRIDE + c] = hp;
        *(__nv_bfloat162*)&Al[row * ASTRIDE + c] = lp;
    }
}

template <int KIN>
__device__ __forceinline__ void mlp_side(char* sm, uint32_t sb,
                                         const float* __restrict__ Xin,
                                         const float* __restrict__ W1,
                                         const float* __restrict__ b1,
                                         int wslot, float (&acc)[2][8][4],
                                         int tid, int wid, int lane, int row0) {
    const __nv_bfloat16* Ah = (const __nv_bfloat16*)(sm + O_AH);
    const __nv_bfloat16* Al = (const __nv_bfloat16*)(sm + O_AL);
    const __nv_bfloat16* Wh = (const __nv_bfloat16*)(sm + O_WH);
    const __nv_bfloat16* Wl = (const __nv_bfloat16*)(sm + O_WH + 18432);

    stage_wt_half(sb + O_WH, wslot, 0, tid);
    CP_COMMIT;
    for (int i = tid; i < 32 * KIN; i += 256)
        ((float4*)(sm + O_XS))[i] = ((const float4*)(Xin + (size_t)row0 * KIN))[i];
    for (int i = tid; i < 32 * KIN; i += 256)
        ((float4*)(sm + O_W1S))[i] = ((const float4*)W1)[i];
    __syncthreads();
    buildH<KIN>(sm, b1, tid);
    CP_WAIT(0);
    __syncthreads();
    zero_acc(acc);
    mma_gemm_half(Ah, Al, Wh, Wl, 0, acc, wid, lane);
    __syncthreads();
    stage_wt_half(sb + O_WH, wslot, 1, tid);
    CP_COMMIT;
    CP_WAIT(0);
    __syncthreads();
    mma_gemm_half(Ah, Al, Wh, Wl, 64, acc, wid, lane);
    __syncthreads();
}

__global__ void __launch_bounds__(256)
k_mlp_fused(const float* __restrict__ Xf, const float* __restrict__ Wf1, const float* __restrict__ bf1,
            const float* __restrict__ bf2,
            const float* __restrict__ Xt, const float* __restrict__ Wt1, const float* __restrict__ bt1,
            const float* __restrict__ bt2,
            float* __restrict__ outdoc) {
    extern __shared__ char sm[];
    uint32_t sb = smem_u32(sm);
    int tid = threadIdx.x, wid = tid >> 5, lane = tid & 31;
    int row0 = blockIdx.x * 128;

    float accF[2][8][4], accT[2][8][4];
    mlp_side<16>(sm, sb, Xf, Wf1, bf1, 3, accF, tid, wid, lane, row0);
    mlp_side<8>(sm, sb, Xt, Wt1, bt1, 4, accT, tid, wid, lane, row0);

    int m0 = (wid & 3) * 32, n0 = (wid >> 2) * 64;
    int g = lane >> 2, t = lane & 3;
#pragma unroll
    for (int i = 0; i < 2; i++)
#pragma unroll
        for (int j = 0; j < 8; j++) {
            int row = m0 + i * 16 + g, col = n0 + j * 8 + t * 2;
            float fa = __ldg(&bf2[col]), fb = __ldg(&bf2[col + 1]);
            float ta = __ldg(&bt2[col]), tb = __ldg(&bt2[col + 1]);
            float2* p = (float2*)&outdoc[(size_t)(row0 + row) * 128 + col];
            float2 o = *p;
            o.x *= (accF[i][j][0] + fa) * (accT[i][j][0] + ta);
            o.y *= (accF[i][j][1] + fb) * (accT[i][j][1] + tb);
            *p = o;
            p = (float2*)&outdoc[(size_t)(row0 + row + 8) * 128 + col];
            o = *p;
            o.x *= (accF[i][j][2] + fa) * (accT[i][j][2] + ta);
            o.y *= (accF[i][j][3] + fb) * (accT[i][j][3] + tb);
            *p = o;
        }
}

// ---------------- launch ----------------------------------------------------
extern "C" void kernel_launch(void* const* d_in, const int* in_sizes, int n_in,
                              void* d_out, int out_size) {
    const float* X   = (const float*)d_in[0];
    const float* Xfb = (const float*)d_in[1];
    const float* Xt  = (const float*)d_in[2];
    const int* e_kw2doc = (const int*)d_in[3];
    const float* W0  = (const float*)d_in[6];
    const float* b0  = (const float*)d_in[7];
    const float* Wg1 = (const float*)d_in[8];
    const float* bg1 = (const float*)d_in[9];
    const float* Wg2 = (const float*)d_in[10];
    const float* bg2 = (const float*)d_in[11];
    const float* Wf1 = (const float*)d_in[12];
    const float* bf1 = (const float*)d_in[13];
    const float* Wf2 = (const float*)d_in[14];
    const float* bf2 = (const float*)d_in[15];
    const float* Wt1 = (const float*)d_in[16];
    const float* bt1 = (const float*)d_in[17];
    const float* Wt2 = (const float*)d_in[18];
    const float* bt2 = (const float*)d_in[19];
    float* out = (float*)d_out;
    float* outdoc = out + (size_t)NKW * D;
    const int* src = e_kw2doc;
    const int* dst = e_kw2doc + EDGES;

    cudaFuncSetAttribute(k_gemm_one<0, 1>, cudaFuncAttributeMaxDynamicSharedMemorySize, SMEM_GEMM);
    cudaFuncSetAttribute(k_gemm_one<1, 0>, cudaFuncAttributeMaxDynamicSharedMemorySize, SMEM_GEMM);
    cudaFuncSetAttribute(k_mlp_fused, cudaFuncAttributeMaxDynamicSharedMemorySize, SMEM_MLP);

    // init counters + weight pre-tiling, then bucketed adjacency build
    k_prep<<<320, 256>>>(W0, Wg1, Wg2, Wf2, Wt2);
    k_fill_bkt<<<EDGES / 256, 256>>>(src, dst);

    // h0 = relu(X W0 + b0) -> g_h0
    k_gemm_one<0, 1><<<NKW / 128, 256, SMEM_GEMM>>>(X, b0, nullptr, 0);

    // layer 1: aggregate h0 kw->doc into g_agg, then docx = relu(g_agg Wg1 + bg1)
    k_gather1<<<NDOC / 8, 256>>>();
    k_gemm_one<1, 0><<<NDOC / 128, 256, SMEM_GEMM>>>(nullptr, bg1, outdoc, 1);

    // layer 2: aggregate docx doc->kw (+ self h0/deg) into g_agg, then kwx = relu(g_agg Wg2 + bg2)
    k_gather2<<<NKW / 8, 256>>>(outdoc);
    k_gemm_one<1, 0><<<NKW / 128, 256, SMEM_GEMM>>>(nullptr, bg2, out, 2);

    // feedback + time MLPs multiplied into doc rows (single RMW)
    k_mlp_fused<<<NDOC / 128, 256, SMEM_MLP>>>(Xfb, Wf1, bf1, bf2,
                                               Xt, Wt1, bt1, bt2, outdoc);
}

// round 14
// speedup vs baseline: 1.1366x; 1.0489x over previous
#include <cuda_runtime.h>
#include <cuda_bf16.h>
#include <cstdint>
#include <cstddef>

#define NKW   65536
#define NDOC  65536
#define EDGES 1048576
#define D     128
#define ASTRIDE 136   // bf16 elems per A smem row (272B, conflict-free)
#define WSTRIDE 72    // bf16 elems per W-half smem row (144B, conflict-free)

// ---------------- scratch (device-side only; never referenced from host) ----
__device__ float g_h0[(size_t)NKW * D];
__device__ float g_agg[(size_t)NDOC * D];
__device__ int g_cntD[NDOC];
__device__ int g_cntK[NKW];
__device__ int g_bktD[(size_t)NDOC * 64];
__device__ int g_bktK[(size_t)NKW * 64];
// pre-tiled weights: [wslot][khalf][hi/lo][n*64 + kloc]; slots 0=W0 1=Wg1 2=Wg2 3=Wf2 4=Wt2
__device__ __nv_bfloat16 g_wt[5 * 2 * 2 * 8192];

// ---------------- init + weight pre-tiling (one launch) --------------------
__global__ void k_prep(const float* __restrict__ W0, const float* __restrict__ Wg1,
                       const float* __restrict__ Wg2, const float* __restrict__ Wf2,
                       const float* __restrict__ Wt2) {
    int idx = blockIdx.x * blockDim.x + threadIdx.x;
    if (idx < NDOC) g_cntD[idx] = 0;
    if (idx < NKW)  g_cntK[idx] = 0;
    if (idx >= 5 * 16384) return;
    int w = idx >> 14;
    int r = idx & 16383;
    int k = r >> 7, n = r & 127;
    const float* W = (w == 0) ? W0 : (w == 1) ? Wg1 : (w == 2) ? Wg2 : (w == 3) ? Wf2 : Wt2;
    float v = W[k * 128 + n];
    __nv_bfloat16 h = __float2bfloat16(v);
    size_t off = (size_t)w * 32768 + (size_t)(k >> 6) * 16384 + (size_t)n * 64 + (k & 63);
    g_wt[off] = h;
    g_wt[off + 8192] = __float2bfloat16(v - __bfloat162float(h));
}

// ---------------- mma.sync GEMM machinery ----------------------------------
// smem layout (bytes): A hi 34816 | A lo 34816 | W half hi 18432 | W half lo 18432
#define O_AH 0
#define O_AL 34816
#define O_WH 69632
#define SMEM_GEMM 106496

__device__ __forceinline__ uint32_t smem_u32(const void* p) {
    uint32_t a;
    asm("{ .reg .u64 t; cvta.to.shared.u64 t, %1; cvt.u32.u64 %0, t; }" : "=r"(a) : "l"(p));
    return a;
}

#define CP_COMMIT asm volatile("cp.async.commit_group;" ::: "memory")
#define CP_WAIT(N) asm volatile("cp.async.wait_group %0;" :: "n"(N) : "memory")

__device__ __forceinline__ void cp16(uint32_t dst, const void* src) {
    asm volatile("cp.async.cg.shared.global [%0], [%1], 16;" :: "r"(dst), "l"(src) : "memory");
}

// stream one k-half of a pre-tiled weight (hi+lo, 32KB) into smem at dstb
__device__ __forceinline__ void stage_wt_half(uint32_t dstb, int wslot, int half, int tid) {
    const __nv_bfloat16* base = g_wt + (size_t)wslot * 32768 + (size_t)half * 16384;
#pragma unroll
    for (int it = 0; it < 8; it++) {
        int i = tid + it * 256;
        int hl = i >> 10;
        int idx = i & 1023;
        int n = idx >> 3;
        int c = idx & 7;
        cp16(dstb + hl * 18432 + n * 144 + c * 16, base + hl * 8192 + n * 64 + c * 8);
    }
}

__device__ __forceinline__ void mma16816(float* c, uint32_t a0, uint32_t a1, uint32_t a2, uint32_t a3,
                                         uint32_t b0, uint32_t b1) {
    asm volatile(
        "mma.sync.aligned.m16n8k16.row.col.f32.bf16.bf16.f32 "
        "{%0,%1,%2,%3}, {%4,%5,%6,%7}, {%8,%9}, {%0,%1,%2,%3};"
        : "+f"(c[0]), "+f"(c[1]), "+f"(c[2]), "+f"(c[3])
        : "r"(a0), "r"(a1), "r"(a2), "r"(a3), "r"(b0), "r"(b1));
}

__device__ __forceinline__ void zero_acc(float (&acc)[2][8][4]) {
#pragma unroll
    for (int i = 0; i < 2; i++)
#pragma unroll
        for (int j = 0; j < 8; j++)
#pragma unroll
            for (int q = 0; q < 4; q++) acc[i][j][q] = 0.f;
}

// acc += A(:, kk0..kk0+63) * Whalf^T, 3-split bf16; B fragments loaded per-j.
__device__ __forceinline__ void mma_gemm_half(const __nv_bfloat16* __restrict__ Ah,
                                              const __nv_bfloat16* __restrict__ Al,
                                              const __nv_bfloat16* __restrict__ Bh,
                                              const __nv_bfloat16* __restrict__ Bl,
                                              int kk0, float (&acc)[2][8][4], int wid, int lane) {
    int m0 = (wid & 3) * 32, n0 = (wid >> 2) * 64;
    int g = lane >> 2, t = lane & 3;
#pragma unroll
    for (int kk = 0; kk < 64; kk += 16) {
        uint32_t ah[2][4], al[2][4];
#pragma unroll
        for (int i = 0; i < 2; i++) {
            const __nv_bfloat16* b = &Ah[(m0 + i * 16 + g) * ASTRIDE + kk0 + kk + t * 2];
            ah[i][0] = *(const uint32_t*)b;
            ah[i][1] = *(const uint32_t*)(b + 8 * ASTRIDE);
            ah[i][2] = *(const uint32_t*)(b + 8);
            ah[i][3] = *(const uint32_t*)(b + 8 * ASTRIDE + 8);
            const __nv_bfloat16* bl2 = &Al[(m0 + i * 16 + g) * ASTRIDE + kk0 + kk + t * 2];
            al[i][0] = *(const uint32_t*)bl2;
            al[i][1] = *(const uint32_t*)(bl2 + 8 * ASTRIDE);
            al[i][2] = *(const uint32_t*)(bl2 + 8);
            al[i][3] = *(const uint32_t*)(bl2 + 8 * ASTRIDE + 8);
        }
#pragma unroll
        for (int j = 0; j < 8; j++) {
            const __nv_bfloat16* b = &Bh[(n0 + j * 8 + g) * WSTRIDE + kk + t * 2];
            uint32_t bh0 = *(const uint32_t*)b;
            uint32_t bh1 = *(const uint32_t*)(b + 8);
            const __nv_bfloat16* b2 = &Bl[(n0 + j * 8 + g) * WSTRIDE + kk + t * 2];
            uint32_t bl0 = *(const uint32_t*)b2;
            uint32_t bl1 = *(const uint32_t*)(b2 + 8);
#pragma unroll
            for (int i = 0; i < 2; i++) {
                mma16816(acc[i][j], ah[i][0], ah[i][1], ah[i][2], ah[i][3], bh0, bh1);
                mma16816(acc[i][j], ah[i][0], ah[i][1], ah[i][2], ah[i][3], bl0, bl1);
                mma16816(acc[i][j], al[i][0], al[i][1], al[i][2], al[i][3], bh0, bh1);
            }
        }
    }
}

__device__ __forceinline__ void split_pair(float v0, float v1, __nv_bfloat162* hp, __nv_bfloat162* lp) {
    __nv_bfloat16 h0 = __float2bfloat16(v0), h1 = __float2bfloat16(v1);
    hp->x = h0; hp->y = h1;
    lp->x = __float2bfloat16(v0 - __bfloat162float(h0));
    lp->y = __float2bfloat16(v1 - __bfloat162float(h1));
}

// fp32 rows -> bf16 hi/lo A tiles (float4 loads, 8B packed stores)
__device__ __forceinline__ void conv_rows(const float* __restrict__ src, char* sm, int tid) {
    __nv_bfloat16* Ah = (__nv_bfloat16*)(sm + O_AH);
    __nv_bfloat16* Al = (__nv_bfloat16*)(sm + O_AL);
    for (int i = tid; i < 4096; i += 256) {
        int row = i >> 5, c = (i & 31) * 4;
        float4 v = *(const float4*)(src + (size_t)row * 128 + c);
        __nv_bfloat162 hp0, lp0, hp1, lp1;
        split_pair(v.x, v.y, &hp0, &lp0);
        split_pair(v.z, v.w, &hp1, &lp1);
        __nv_bfloat162* ph = (__nv_bfloat162*)&Ah[row * ASTRIDE + c];
        ph[0] = hp0; ph[1] = hp1;
        __nv_bfloat162* pl = (__nv_bfloat162*)&Al[row * ASTRIDE + c];
        pl[0] = lp0; pl[1] = lp1;
    }
}

// epilogue: dst = relu(acc + bias)
__device__ __forceinline__ void epi_relu(float* __restrict__ dst, int row0, const float* __restrict__ bias,
                                         float (&acc)[2][8][4], int wid, int lane) {
    int m0 = (wid & 3) * 32, n0 = (wid >> 2) * 64;
    int g = lane >> 2, t = lane & 3;
#pragma unroll
    for (int i = 0; i < 2; i++)
#pragma unroll
        for (int j = 0; j < 8; j++) {
            int row = m0 + i * 16 + g, col = n0 + j * 8 + t * 2;
            float ba = __ldg(&bias[col]), bb = __ldg(&bias[col + 1]);
            *(float2*)&dst[(size_t)(row0 + row) * 128 + col] =
                make_float2(fmaxf(acc[i][j][0] + ba, 0.f), fmaxf(acc[i][j][1] + bb, 0.f));
            *(float2*)&dst[(size_t)(row0 + row + 8) * 128 + col] =
                make_float2(fmaxf(acc[i][j][2] + ba, 0.f), fmaxf(acc[i][j][3] + bb, 0.f));
        }
}

// full 128x128 GEMM tile: dst = relu(A @ Wt[wslot] + bias)
__device__ __forceinline__ void gemm_tile(const float* __restrict__ A, const float* __restrict__ bias,
                                          float* __restrict__ dst, int wslot, int row0,
                                          char* sm, uint32_t sb, int tid, int wid, int lane) {
    const __nv_bfloat16* Ah = (const __nv_bfloat16*)(sm + O_AH);
    const __nv_bfloat16* Al = (const __nv_bfloat16*)(sm + O_AL);
    const __nv_bfloat16* Wh = (const __nv_bfloat16*)(sm + O_WH);
    const __nv_bfloat16* Wl = (const __nv_bfloat16*)(sm + O_WH + 18432);

    stage_wt_half(sb + O_WH, wslot, 0, tid);
    CP_COMMIT;
    conv_rows(A + (size_t)row0 * 128, sm, tid);
    CP_WAIT(0);
    __syncthreads();

    float acc[2][8][4];
    zero_acc(acc);
    mma_gemm_half(Ah, Al, Wh, Wl, 0, acc, wid, lane);
    __syncthreads();
    stage_wt_half(sb + O_WH, wslot, 1, tid);
    CP_COMMIT;
    CP_WAIT(0);
    __syncthreads();
    mma_gemm_half(Ah, Al, Wh, Wl, 64, acc, wid, lane);
    epi_relu(dst, row0, bias, acc, wid, lane);
}

// ------------- merged: layer-0 GEMM (blocks<512) + bucket fill (rest) --------
__global__ void __launch_bounds__(256, 2)
k_fill_gemm0(const float* __restrict__ X, const float* __restrict__ b0,
             const int* __restrict__ src, const int* __restrict__ dst) {
    extern __shared__ char sm[];
    int tid = threadIdx.x;
    if (blockIdx.x < 512) {
        uint32_t sb = smem_u32(sm);
        gemm_tile(X, b0, g_h0, 0, blockIdx.x * 128, sm, sb, tid, tid >> 5, tid & 31);
    } else {
        int i = (blockIdx.x - 512) * 256 + tid;   // covers EDGES exactly (4096*256)
        int s = src[i];
        int dl = dst[i] - NKW;
        int p = atomicAdd(&g_cntD[dl], 1);
        if (p < 64) g_bktD[(size_t)dl * 64 + p] = s;
        int q = atomicAdd(&g_cntK[s], 1);
        if (q < 64) g_bktK[(size_t)s * 64 + q] = dl;
    }
}

// ------------- layer-1 GEMM: outdoc = relu(g_agg Wg1 + bg1) ------------------
__global__ void __launch_bounds__(256, 2)
k_gemm1(const float* __restrict__ bias, float* __restrict__ dst) {
    extern __shared__ char sm[];
    uint32_t sb = smem_u32(sm);
    int tid = threadIdx.x;
    gemm_tile(g_agg, bias, dst, 1, blockIdx.x * 128, sm, sb, tid, tid >> 5, tid & 31);
}

// ------------- gathers (unroll 8) --------------------------------------------
__device__ __forceinline__ void acc_add(float4& a, const float4& v) {
    a.x += v.x; a.y += v.y; a.z += v.z; a.w += v.w;
}

__device__ __forceinline__ float4 gather_core(const float* __restrict__ S,
                                              const int* __restrict__ bkt,
                                              int n, int lane) {
    int m1 = bkt[lane];
    int m2 = bkt[32 + lane];
    float4 a0 = make_float4(0.f, 0.f, 0.f, 0.f), a1 = a0;
    int n1 = n < 32 ? n : 32;
    int e = 0;
    for (; e + 8 <= n1; e += 8) {
        int i0 = __shfl_sync(0xFFFFFFFFu, m1, e);
        int i1 = __shfl_sync(0xFFFFFFFFu, m1, e + 1);
        int i2 = __shfl_sync(0xFFFFFFFFu, m1, e + 2);
        int i3 = __shfl_sync(0xFFFFFFFFu, m1, e + 3);
        int i4 = __shfl_sync(0xFFFFFFFFu, m1, e + 4);
        int i5 = __shfl_sync(0xFFFFFFFFu, m1, e + 5);
        int i6 = __shfl_sync(0xFFFFFFFFu, m1, e + 6);
        int i7 = __shfl_sync(0xFFFFFFFFu, m1, e + 7);
        float4 v0 = *(const float4*)&S[(size_t)i0 * D + lane * 4];
        float4 v1 = *(const float4*)&S[(size_t)i1 * D + lane * 4];
        float4 v2 = *(const float4*)&S[(size_t)i2 * D + lane * 4];
        float4 v3 = *(const float4*)&S[(size_t)i3 * D + lane * 4];
        float4 v4 = *(const float4*)&S[(size_t)i4 * D + lane * 4];
        float4 v5 = *(const float4*)&S[(size_t)i5 * D + lane * 4];
        float4 v6 = *(const float4*)&S[(size_t)i6 * D + lane * 4];
        float4 v7 = *(const float4*)&S[(size_t)i7 * D + lane * 4];
        acc_add(a0, v0); acc_add(a1, v1); acc_add(a0, v2); acc_add(a1, v3);
        acc_add(a0, v4); acc_add(a1, v5); acc_add(a0, v6); acc_add(a1, v7);
    }
    for (; e + 4 <= n1; e += 4) {
        int i0 = __shfl_sync(0xFFFFFFFFu, m1, e);
        int i1 = __shfl_sync(0xFFFFFFFFu, m1, e + 1);
        int i2 = __shfl_sync(0xFFFFFFFFu, m1, e + 2);
        int i3 = __shfl_sync(0xFFFFFFFFu, m1, e + 3);
        float4 v0 = *(const float4*)&S[(size_t)i0 * D + lane * 4];
        float4 v1 = *(const float4*)&S[(size_t)i1 * D + lane * 4];
        float4 v2 = *(const float4*)&S[(size_t)i2 * D + lane * 4];
        float4 v3 = *(const float4*)&S[(size_t)i3 * D + lane * 4];
        acc_add(a0, v0); acc_add(a1, v1); acc_add(a0, v2); acc_add(a1, v3);
    }
    for (; e < n1; e++) {
        int i0 = __shfl_sync(0xFFFFFFFFu, m1, e);
        float4 v = *(const float4*)&S[(size_t)i0 * D + lane * 4];
        acc_add(a0, v);
    }
    for (e = 32; e + 4 <= n; e += 4) {
        int i0 = __shfl_sync(0xFFFFFFFFu, m2, e - 32);
        int i1 = __shfl_sync(0xFFFFFFFFu, m2, e - 31);
        int i2 = __shfl_sync(0xFFFFFFFFu, m2, e - 30);
        int i3 = __shfl_sync(0xFFFFFFFFu, m2, e - 29);
        float4 v0 = *(const float4*)&S[(size_t)i0 * D + lane * 4];
        float4 v1 = *(const float4*)&S[(size_t)i1 * D + lane * 4];
        float4 v2 = *(const float4*)&S[(size_t)i2 * D + lane * 4];
        float4 v3 = *(const float4*)&S[(size_t)i3 * D + lane * 4];
        acc_add(a0, v0); acc_add(a1, v1); acc_add(a0, v2); acc_add(a1, v3);
    }
    for (; e < n; e++) {
        int i0 = __shfl_sync(0xFFFFFFFFu, m2, e - 32);
        float4 v = *(const float4*)&S[(size_t)i0 * D + lane * 4];
        acc_add(a1, v);
    }
    float4 r;
    r.x = a0.x + a1.x; r.y = a0.y + a1.y; r.z = a0.z + a1.z; r.w = a0.w + a1.w;
    return r;
}

__global__ void k_gather1() {
    int w = (blockIdx.x * blockDim.x + threadIdx.x) >> 5;
    int lane = threadIdx.x & 31;
    if (w >= NDOC) return;
    int n = min(g_cntD[w], 64);
    float4 r = gather_core(g_h0, &g_bktD[(size_t)w * 64], n, lane);
    float s = rsqrtf((float)(n + 1));
    r.x *= s; r.y *= s; r.z *= s; r.w *= s;
    *(float4*)&g_agg[(size_t)w * D + lane * 4] = r;
}

__global__ void k_gather2(const float* __restrict__ docx) {
    int k = (blockIdx.x * blockDim.x + threadIdx.x) >> 5;
    int lane = threadIdx.x & 31;
    if (k >= NKW) return;
    int n = min(g_cntK[k], 64);
    float4 r = gather_core(docx, &g_bktK[(size_t)k * 64], n, lane);
    float deg = (float)(n + 1);
    float s = rsqrtf(deg);
    float inv = 1.f / deg;
    float4 hk = *(const float4*)&g_h0[(size_t)k * D + lane * 4];
    r.x = r.x * s + hk.x * inv;
    r.y = r.y * s + hk.y * inv;
    r.z = r.z * s + hk.z * inv;
    r.w = r.w * s + hk.w * inv;
    *(float4*)&g_agg[(size_t)k * D + lane * 4] = r;
}

// ------------- MLP pieces (XS/W1S overlaid into the WH region) ---------------
template <int KIN>
__device__ __forceinline__ void buildH2(char* sm, const float* __restrict__ b1, int tid) {
    const float* XS = (const float*)(sm + O_WH);
    const float* W1 = (const float*)(sm + O_WH + 8192);
    __nv_bfloat16* Ah = (__nv_bfloat16*)(sm + O_AH);
    __nv_bfloat16* Al = (__nv_bfloat16*)(sm + O_AL);
    for (int i = tid; i < 8192; i += 256) {
        int row = i >> 6, c = (i & 63) * 2;
        float a0 = __ldg(&b1[c]), a1 = __ldg(&b1[c + 1]);
#pragma unroll
        for (int k = 0; k < KIN; k++) {
            float x = XS[row * KIN + k];
            a0 = fmaf(x, W1[k * 128 + c], a0);
            a1 = fmaf(x, W1[k * 128 + c + 1], a1);
        }
        __nv_bfloat162 hp, lp;
        split_pair(fmaxf(a0, 0.f), fmaxf(a1, 0.f), &hp, &lp);
        *(__nv_bfloat162*)&Ah[row * ASTRIDE + c] = hp;
        *(__nv_bfloat162*)&Al[row * ASTRIDE + c] = lp;
    }
}

template <int KIN>
__device__ __forceinline__ void mlp_side2(char* sm, uint32_t sb,
                                          const float* __restrict__ Xin,
                                          const float* __restrict__ W1,
                                          const float* __restrict__ b1,
                                          int wslot, float (&acc)[2][8][4],
                                          int tid, int wid, int lane, int row0) {
    const __nv_bfloat16* Ah = (const __nv_bfloat16*)(sm + O_AH);
    const __nv_bfloat16* Al = (const __nv_bfloat16*)(sm + O_AL);
    const __nv_bfloat16* Wh = (const __nv_bfloat16*)(sm + O_WH);
    const __nv_bfloat16* Wl = (const __nv_bfloat16*)(sm + O_WH + 18432);

    // stage XS / W1S into the (currently unused) WH region
    for (int i = tid; i < 32 * KIN; i += 256)
        ((float4*)(sm + O_WH))[i] = ((const float4*)(Xin + (size_t)row0 * KIN))[i];
    for (int i = tid; i < 32 * KIN; i += 256)
        ((float4*)(sm + O_WH + 8192))[i] = ((const float4*)W1)[i];
    __syncthreads();
    buildH2<KIN>(sm, b1, tid);
    __syncthreads();                 // done reading XS/W1S; WH free for weights

    stage_wt_half(sb + O_WH, wslot, 0, tid);
    CP_COMMIT;
    CP_WAIT(0);
    __syncthreads();
    zero_acc(acc);
    mma_gemm_half(Ah, Al, Wh, Wl, 0, acc, wid, lane);
    __syncthreads();
    stage_wt_half(sb + O_WH, wslot, 1, tid);
    CP_COMMIT;
    CP_WAIT(0);
    __syncthreads();
    mma_gemm_half(Ah, Al, Wh, Wl, 64, acc, wid, lane);
    __syncthreads();
}

// out[row][col] *= (acc + b2)  (RMW, one side at a time keeps regs < 128)
__device__ __forceinline__ void mul_out(float* __restrict__ outdoc, int row0, const float* __restrict__ b2,
                                        float (&acc)[2][8][4], int wid, int lane) {
    int m0 = (wid & 3) * 32, n0 = (wid >> 2) * 64;
    int g = lane >> 2, t = lane & 3;
#pragma unroll
    for (int i = 0; i < 2; i++)
#pragma unroll
        for (int j = 0; j < 8; j++) {
            int row = m0 + i * 16 + g, col = n0 + j * 8 + t * 2;
            float ba = __ldg(&b2[col]), bb = __ldg(&b2[col + 1]);
            float2* p = (float2*)&outdoc[(size_t)(row0 + row) * 128 + col];
            float2 o = *p;
            o.x *= acc[i][j][0] + ba;
            o.y *= acc[i][j][1] + bb;
            *p = o;
            p = (float2*)&outdoc[(size_t)(row0 + row + 8) * 128 + col];
            o = *p;
            o.x *= acc[i][j][2] + ba;
            o.y *= acc[i][j][3] + bb;
            *p = o;
        }
}

// ------------- merged: layer-2 GEMM (blocks<512) + feedback/time MLP (rest) --
__global__ void __launch_bounds__(256, 2)
k_gemm2_mlp(const float* __restrict__ bg2, float* __restrict__ out, float* __restrict__ outdoc,
            const float* __restrict__ Xf, const float* __restrict__ Wf1, const float* __restrict__ bf1,
            const float* __restrict__ bf2,
            const float* __restrict__ Xt, const float* __restrict__ Wt1, const float* __restrict__ bt1,
            const float* __restrict__ bt2) {
    extern __shared__ char sm[];
    uint32_t sb = smem_u32(sm);
    int tid = threadIdx.x, wid = tid >> 5, lane = tid & 31;
    if (blockIdx.x < 512) {
        gemm_tile(g_agg, bg2, out, 2, blockIdx.x * 128, sm, sb, tid, wid, lane);
    } else {
        int row0 = (blockIdx.x - 512) * 128;
        float acc[2][8][4];
        mlp_side2<16>(sm, sb, Xf, Wf1, bf1, 3, acc, tid, wid, lane, row0);
        mul_out(outdoc, row0, bf2, acc, wid, lane);
        mlp_side2<8>(sm, sb, Xt, Wt1, bt1, 4, acc, tid, wid, lane, row0);
        mul_out(outdoc, row0, bt2, acc, wid, lane);
    }
}

// ---------------- launch ----------------------------------------------------
extern "C" void kernel_launch(void* const* d_in, const int* in_sizes, int n_in,
                              void* d_out, int out_size) {
    const float* X   = (const float*)d_in[0];
    const float* Xfb = (const float*)d_in[1];
    const float* Xt  = (const float*)d_in[2];
    const int* e_kw2doc = (const int*)d_in[3];
    const float* W0  = (const float*)d_in[6];
    const float* b0  = (const float*)d_in[7];
    const float* Wg1 = (const float*)d_in[8];
    const float* bg1 = (const float*)d_in[9];
    const float* Wg2 = (const float*)d_in[10];
    const float* bg2 = (const float*)d_in[11];
    const float* Wf1 = (const float*)d_in[12];
    const float* bf1 = (const float*)d_in[13];
    const float* Wf2 = (const float*)d_in[14];
    const float* bf2 = (const float*)d_in[15];
    const float* Wt1 = (const float*)d_in[16];
    const float* bt1 = (const float*)d_in[17];
    const float* Wt2 = (const float*)d_in[18];
    const float* bt2 = (const float*)d_in[19];
    float* out = (float*)d_out;
    float* outdoc = out + (size_t)NKW * D;
    const int* src = e_kw2doc;
    const int* dst = e_kw2doc + EDGES;

    cudaFuncSetAttribute(k_fill_gemm0, cudaFuncAttributeMaxDynamicSharedMemorySize, SMEM_GEMM);
    cudaFuncSetAttribute(k_gemm1, cudaFuncAttributeMaxDynamicSharedMemorySize, SMEM_GEMM);
    cudaFuncSetAttribute(k_gemm2_mlp, cudaFuncAttributeMaxDynamicSharedMemorySize, SMEM_GEMM);

    // init counters + weight pre-tiling
    k_prep<<<320, 256>>>(W0, Wg1, Wg2, Wf2, Wt2);

    // merged: layer-0 GEMM (h0) + bucket fill (independent work)
    k_fill_gemm0<<<512 + EDGES / 256, 256, SMEM_GEMM>>>(X, b0, src, dst);

    // layer 1: aggregate h0 kw->doc into g_agg, then docx = relu(g_agg Wg1 + bg1)
    k_gather1<<<NDOC / 8, 256>>>();
    k_gemm1<<<NDOC / 128, 256, SMEM_GEMM>>>(bg1, outdoc);

    // layer 2 aggregation
    k_gather2<<<NKW / 8, 256>>>(outdoc);

    // merged: layer-2 GEMM (kw rows) + feedback/time MLP (doc rows RMW)
    k_gemm2_mlp<<<1024, 256, SMEM_GEMM>>>(bg2, out, outdoc,
                                          Xfb, Wf1, bf1, bf2, Xt, Wt1, bt1, bt2);
}

// round 15
// speedup vs baseline: 1.1866x; 1.0440x over previous
#include <cuda_runtime.h>
#include <cuda_bf16.h>
#include <cstdint>
#include <cstddef>

#define NKW   65536
#define NDOC  65536
#define EDGES 1048576
#define D     128
#define ASTRIDE 136   // bf16 elems per A smem row (272B, conflict-free)
#define WSTRIDE 72    // bf16 elems per W-half smem row (144B, conflict-free)

// ---------------- scratch (device-side only; never referenced from host) ----
__device__ float g_h0[(size_t)NKW * D];
__device__ float g_agg[(size_t)NDOC * D];
__device__ int g_cntD[NDOC];
__device__ int g_cntK[NKW];
__device__ int g_bktD[(size_t)NDOC * 64];
__device__ int g_bktK[(size_t)NKW * 64];
// pre-tiled weights: [wslot][khalf][hi/lo][n*64 + kloc]; slots 0=W0 1=Wg1 2=Wg2 3=Wf2 4=Wt2
__device__ __nv_bfloat16 g_wt[5 * 2 * 2 * 8192];

// ---------------- init + weight pre-tiling (one launch) --------------------
__global__ void k_prep(const float* __restrict__ W0, const float* __restrict__ Wg1,
                       const float* __restrict__ Wg2, const float* __restrict__ Wf2,
                       const float* __restrict__ Wt2) {
    int idx = blockIdx.x * blockDim.x + threadIdx.x;
    if (idx < NDOC) g_cntD[idx] = 0;
    if (idx < NKW)  g_cntK[idx] = 0;
    if (idx >= 5 * 16384) return;
    int w = idx >> 14;
    int r = idx & 16383;
    int k = r >> 7, n = r & 127;
    const float* W = (w == 0) ? W0 : (w == 1) ? Wg1 : (w == 2) ? Wg2 : (w == 3) ? Wf2 : Wt2;
    float v = W[k * 128 + n];
    __nv_bfloat16 h = __float2bfloat16(v);
    size_t off = (size_t)w * 32768 + (size_t)(k >> 6) * 16384 + (size_t)n * 64 + (k & 63);
    g_wt[off] = h;
    g_wt[off + 8192] = __float2bfloat16(v - __bfloat162float(h));
}

// ---------------- mma.sync GEMM machinery (M=64 tiles) ----------------------
// smem layout (bytes): A hi 17408 | A lo 17408 | W half hi 18432 | W half lo 18432
#define O_AH 0
#define O_AL 17408
#define O_WH 34816
#define SMEM_GEMM 71680

__device__ __forceinline__ uint32_t smem_u32(const void* p) {
    uint32_t a;
    asm("{ .reg .u64 t; cvta.to.shared.u64 t, %1; cvt.u32.u64 %0, t; }" : "=r"(a) : "l"(p));
    return a;
}

#define CP_COMMIT asm volatile("cp.async.commit_group;" ::: "memory")
#define CP_WAIT(N) asm volatile("cp.async.wait_group %0;" :: "n"(N) : "memory")

__device__ __forceinline__ void cp16(uint32_t dst, const void* src) {
    asm volatile("cp.async.cg.shared.global [%0], [%1], 16;" :: "r"(dst), "l"(src) : "memory");
}

// stream one k-half of a pre-tiled weight (hi+lo, 32KB) into smem at dstb
__device__ __forceinline__ void stage_wt_half(uint32_t dstb, int wslot, int half, int tid) {
    const __nv_bfloat16* base = g_wt + (size_t)wslot * 32768 + (size_t)half * 16384;
#pragma unroll
    for (int it = 0; it < 8; it++) {
        int i = tid + it * 256;
        int hl = i >> 10;
        int idx = i & 1023;
        int n = idx >> 3;
        int c = idx & 7;
        cp16(dstb + hl * 18432 + n * 144 + c * 16, base + hl * 8192 + n * 64 + c * 8);
    }
}

__device__ __forceinline__ void mma16816(float* c, uint32_t a0, uint32_t a1, uint32_t a2, uint32_t a3,
                                         uint32_t b0, uint32_t b1) {
    asm volatile(
        "mma.sync.aligned.m16n8k16.row.col.f32.bf16.bf16.f32 "
        "{%0,%1,%2,%3}, {%4,%5,%6,%7}, {%8,%9}, {%0,%1,%2,%3};"
        : "+f"(c[0]), "+f"(c[1]), "+f"(c[2]), "+f"(c[3])
        : "r"(a0), "r"(a1), "r"(a2), "r"(a3), "r"(b0), "r"(b1));
}

__device__ __forceinline__ void zero_acc(float (&acc)[8][4]) {
#pragma unroll
    for (int j = 0; j < 8; j++)
#pragma unroll
        for (int q = 0; q < 4; q++) acc[j][q] = 0.f;
}

// warp tile: 16 rows (m0=(wid&3)*16) x 64 cols (n0=(wid>>2)*64)
// acc += A(:, kk0..kk0+63) * Whalf^T, 3-split bf16.
__device__ __forceinline__ void mma_gemm_half(const __nv_bfloat16* __restrict__ Ah,
                                              const __nv_bfloat16* __restrict__ Al,
                                              const __nv_bfloat16* __restrict__ Bh,
                                              const __nv_bfloat16* __restrict__ Bl,
                                              int kk0, float (&acc)[8][4], int wid, int lane) {
    int m0 = (wid & 3) * 16, n0 = (wid >> 2) * 64;
    int g = lane >> 2, t = lane & 3;
#pragma unroll
    for (int kk = 0; kk < 64; kk += 16) {
        uint32_t ah[4], al[4];
        {
            const __nv_bfloat16* b = &Ah[(m0 + g) * ASTRIDE + kk0 + kk + t * 2];
            ah[0] = *(const uint32_t*)b;
            ah[1] = *(const uint32_t*)(b + 8 * ASTRIDE);
            ah[2] = *(const uint32_t*)(b + 8);
            ah[3] = *(const uint32_t*)(b + 8 * ASTRIDE + 8);
            const __nv_bfloat16* bl2 = &Al[(m0 + g) * ASTRIDE + kk0 + kk + t * 2];
            al[0] = *(const uint32_t*)bl2;
            al[1] = *(const uint32_t*)(bl2 + 8 * ASTRIDE);
            al[2] = *(const uint32_t*)(bl2 + 8);
            al[3] = *(const uint32_t*)(bl2 + 8 * ASTRIDE + 8);
        }
#pragma unroll
        for (int j = 0; j < 8; j++) {
            const __nv_bfloat16* b = &Bh[(n0 + j * 8 + g) * WSTRIDE + kk + t * 2];
            uint32_t bh0 = *(const uint32_t*)b;
            uint32_t bh1 = *(const uint32_t*)(b + 8);
            const __nv_bfloat16* b2 = &Bl[(n0 + j * 8 + g) * WSTRIDE + kk + t * 2];
            uint32_t bl0 = *(const uint32_t*)b2;
            uint32_t bl1 = *(const uint32_t*)(b2 + 8);
            mma16816(acc[j], ah[0], ah[1], ah[2], ah[3], bh0, bh1);
            mma16816(acc[j], ah[0], ah[1], ah[2], ah[3], bl0, bl1);
            mma16816(acc[j], al[0], al[1], al[2], al[3], bh0, bh1);
        }
    }
}

__device__ __forceinline__ void split_pair(float v0, float v1, __nv_bfloat162* hp, __nv_bfloat162* lp) {
    __nv_bfloat16 h0 = __float2bfloat16(v0), h1 = __float2bfloat16(v1);
    hp->x = h0; hp->y = h1;
    lp->x = __float2bfloat16(v0 - __bfloat162float(h0));
    lp->y = __float2bfloat16(v1 - __bfloat162float(h1));
}

// fp32 rows (64) -> bf16 hi/lo A tiles
__device__ __forceinline__ void conv_rows(const float* __restrict__ src, char* sm, int tid) {
    __nv_bfloat16* Ah = (__nv_bfloat16*)(sm + O_AH);
    __nv_bfloat16* Al = (__nv_bfloat16*)(sm + O_AL);
    for (int i = tid; i < 2048; i += 256) {
        int row = i >> 5, c = (i & 31) * 4;
        float4 v = *(const float4*)(src + (size_t)row * 128 + c);
        __nv_bfloat162 hp0, lp0, hp1, lp1;
        split_pair(v.x, v.y, &hp0, &lp0);
        split_pair(v.z, v.w, &hp1, &lp1);
        __nv_bfloat162* ph = (__nv_bfloat162*)&Ah[row * ASTRIDE + c];
        ph[0] = hp0; ph[1] = hp1;
        __nv_bfloat162* pl = (__nv_bfloat162*)&Al[row * ASTRIDE + c];
        pl[0] = lp0; pl[1] = lp1;
    }
}

// epilogue: dst = relu(acc + bias), 64-row tile
__device__ __forceinline__ void epi_relu(float* __restrict__ dst, int row0, const float* __restrict__ bias,
                                         float (&acc)[8][4], int wid, int lane) {
    int m0 = (wid & 3) * 16, n0 = (wid >> 2) * 64;
    int g = lane >> 2, t = lane & 3;
#pragma unroll
    for (int j = 0; j < 8; j++) {
        int row = m0 + g, col = n0 + j * 8 + t * 2;
        float ba = __ldg(&bias[col]), bb = __ldg(&bias[col + 1]);
        *(float2*)&dst[(size_t)(row0 + row) * 128 + col] =
            make_float2(fmaxf(acc[j][0] + ba, 0.f), fmaxf(acc[j][1] + bb, 0.f));
        *(float2*)&dst[(size_t)(row0 + row + 8) * 128 + col] =
            make_float2(fmaxf(acc[j][2] + ba, 0.f), fmaxf(acc[j][3] + bb, 0.f));
    }
}

// full 64x128 GEMM tile: dst = relu(A @ Wt[wslot] + bias)
__device__ __forceinline__ void gemm_tile(const float* __restrict__ A, const float* __restrict__ bias,
                                          float* __restrict__ dst, int wslot, int row0,
                                          char* sm, uint32_t sb, int tid, int wid, int lane) {
    const __nv_bfloat16* Ah = (const __nv_bfloat16*)(sm + O_AH);
    const __nv_bfloat16* Al = (const __nv_bfloat16*)(sm + O_AL);
    const __nv_bfloat16* Wh = (const __nv_bfloat16*)(sm + O_WH);
    const __nv_bfloat16* Wl = (const __nv_bfloat16*)(sm + O_WH + 18432);

    stage_wt_half(sb + O_WH, wslot, 0, tid);
    CP_COMMIT;
    conv_rows(A + (size_t)row0 * 128, sm, tid);
    CP_WAIT(0);
    __syncthreads();

    float acc[8][4];
    zero_acc(acc);
    mma_gemm_half(Ah, Al, Wh, Wl, 0, acc, wid, lane);
    __syncthreads();
    stage_wt_half(sb + O_WH, wslot, 1, tid);
    CP_COMMIT;
    CP_WAIT(0);
    __syncthreads();
    mma_gemm_half(Ah, Al, Wh, Wl, 64, acc, wid, lane);
    epi_relu(dst, row0, bias, acc, wid, lane);
}

// ------------- merged: layer-0 GEMM (blocks<1024) + bucket fill (rest) -------
__global__ void __launch_bounds__(256, 3)
k_fill_gemm0(const float* __restrict__ X, const float* __restrict__ b0,
             const int* __restrict__ src, const int* __restrict__ dst) {
    extern __shared__ char sm[];
    int tid = threadIdx.x;
    if (blockIdx.x < 1024) {
        uint32_t sb = smem_u32(sm);
        gemm_tile(X, b0, g_h0, 0, blockIdx.x * 64, sm, sb, tid, tid >> 5, tid & 31);
    } else {
        int i = (blockIdx.x - 1024) * 256 + tid;   // 4096 blocks cover EDGES
        int s = src[i];
        int dl = dst[i] - NKW;
        int p = atomicAdd(&g_cntD[dl], 1);
        if (p < 64) g_bktD[(size_t)dl * 64 + p] = s;
        int q = atomicAdd(&g_cntK[s], 1);
        if (q < 64) g_bktK[(size_t)s * 64 + q] = dl;
    }
}

// ------------- layer-1 GEMM: outdoc = relu(g_agg Wg1 + bg1) ------------------
__global__ void __launch_bounds__(256, 3)
k_gemm1(const float* __restrict__ bias, float* __restrict__ dst) {
    extern __shared__ char sm[];
    uint32_t sb = smem_u32(sm);
    int tid = threadIdx.x;
    gemm_tile(g_agg, bias, dst, 1, blockIdx.x * 64, sm, sb, tid, tid >> 5, tid & 31);
}

// ------------- gathers (unroll 8) --------------------------------------------
__device__ __forceinline__ void acc_add(float4& a, const float4& v) {
    a.x += v.x; a.y += v.y; a.z += v.z; a.w += v.w;
}

__device__ __forceinline__ float4 gather_core(const float* __restrict__ S,
                                              const int* __restrict__ bkt,
                                              int n, int lane) {
    int m1 = bkt[lane];
    int m2 = bkt[32 + lane];
    float4 a0 = make_float4(0.f, 0.f, 0.f, 0.f), a1 = a0;
    int n1 = n < 32 ? n : 32;
    int e = 0;
    for (; e + 8 <= n1; e += 8) {
        int i0 = __shfl_sync(0xFFFFFFFFu, m1, e);
        int i1 = __shfl_sync(0xFFFFFFFFu, m1, e + 1);
        int i2 = __shfl_sync(0xFFFFFFFFu, m1, e + 2);
        int i3 = __shfl_sync(0xFFFFFFFFu, m1, e + 3);
        int i4 = __shfl_sync(0xFFFFFFFFu, m1, e + 4);
        int i5 = __shfl_sync(0xFFFFFFFFu, m1, e + 5);
        int i6 = __shfl_sync(0xFFFFFFFFu, m1, e + 6);
        int i7 = __shfl_sync(0xFFFFFFFFu, m1, e + 7);
        float4 v0 = *(const float4*)&S[(size_t)i0 * D + lane * 4];
        float4 v1 = *(const float4*)&S[(size_t)i1 * D + lane * 4];
        float4 v2 = *(const float4*)&S[(size_t)i2 * D + lane * 4];
        float4 v3 = *(const float4*)&S[(size_t)i3 * D + lane * 4];
        float4 v4 = *(const float4*)&S[(size_t)i4 * D + lane * 4];
        float4 v5 = *(const float4*)&S[(size_t)i5 * D + lane * 4];
        float4 v6 = *(const float4*)&S[(size_t)i6 * D + lane * 4];
        float4 v7 = *(const float4*)&S[(size_t)i7 * D + lane * 4];
        acc_add(a0, v0); acc_add(a1, v1); acc_add(a0, v2); acc_add(a1, v3);
        acc_add(a0, v4); acc_add(a1, v5); acc_add(a0, v6); acc_add(a1, v7);
    }
    for (; e + 4 <= n1; e += 4) {
        int i0 = __shfl_sync(0xFFFFFFFFu, m1, e);
        int i1 = __shfl_sync(0xFFFFFFFFu, m1, e + 1);
        int i2 = __shfl_sync(0xFFFFFFFFu, m1, e + 2);
        int i3 = __shfl_sync(0xFFFFFFFFu, m1, e + 3);
        float4 v0 = *(const float4*)&S[(size_t)i0 * D + lane * 4];
        float4 v1 = *(const float4*)&S[(size_t)i1 * D + lane * 4];
        float4 v2 = *(const float4*)&S[(size_t)i2 * D + lane * 4];
        float4 v3 = *(const float4*)&S[(size_t)i3 * D + lane * 4];
        acc_add(a0, v0); acc_add(a1, v1); acc_add(a0, v2); acc_add(a1, v3);
    }
    for (; e < n1; e++) {
        int i0 = __shfl_sync(0xFFFFFFFFu, m1, e);
        float4 v = *(const float4*)&S[(size_t)i0 * D + lane * 4];
        acc_add(a0, v);
    }
    for (e = 32; e + 4 <= n; e += 4) {
        int i0 = __shfl_sync(0xFFFFFFFFu, m2, e - 32);
        int i1 = __shfl_sync(0xFFFFFFFFu, m2, e - 31);
        int i2 = __shfl_sync(0xFFFFFFFFu, m2, e - 30);
        int i3 = __shfl_sync(0xFFFFFFFFu, m2, e - 29);
        float4 v0 = *(const float4*)&S[(size_t)i0 * D + lane * 4];
        float4 v1 = *(const float4*)&S[(size_t)i1 * D + lane * 4];
        float4 v2 = *(const float4*)&S[(size_t)i2 * D + lane * 4];
        float4 v3 = *(const float4*)&S[(size_t)i3 * D + lane * 4];
        acc_add(a0, v0); acc_add(a1, v1); acc_add(a0, v2); acc_add(a1, v3);
    }
    for (; e < n; e++) {
        int i0 = __shfl_sync(0xFFFFFFFFu, m2, e - 32);
        float4 v = *(const float4*)&S[(size_t)i0 * D + lane * 4];
        acc_add(a1, v);
    }
    float4 r;
    r.x = a0.x + a1.x; r.y = a0.y + a1.y; r.z = a0.z + a1.z; r.w = a0.w + a1.w;
    return r;
}

__global__ void k_gather1() {
    int w = (blockIdx.x * blockDim.x + threadIdx.x) >> 5;
    int lane = threadIdx.x & 31;
    if (w >= NDOC) return;
    int n = min(g_cntD[w], 64);
    float4 r = gather_core(g_h0, &g_bktD[(size_t)w * 64], n, lane);
    float s = rsqrtf((float)(n + 1));
    r.x *= s; r.y *= s; r.z *= s; r.w *= s;
    *(float4*)&g_agg[(size_t)w * D + lane * 4] = r;
}

__global__ void k_gather2(const float* __restrict__ docx) {
    int k = (blockIdx.x * blockDim.x + threadIdx.x) >> 5;
    int lane = threadIdx.x & 31;
    if (k >= NKW) return;
    int n = min(g_cntK[k], 64);
    float4 r = gather_core(docx, &g_bktK[(size_t)k * 64], n, lane);
    float deg = (float)(n + 1);
    float s = rsqrtf(deg);
    float inv = 1.f / deg;
    float4 hk = *(const float4*)&g_h0[(size_t)k * D + lane * 4];
    r.x = r.x * s + hk.x * inv;
    r.y = r.y * s + hk.y * inv;
    r.z = r.z * s + hk.z * inv;
    r.w = r.w * s + hk.w * inv;
    *(float4*)&g_agg[(size_t)k * D + lane * 4] = r;
}

// ------------- MLP pieces (M=64 tiles; XS/W1S overlaid into WH region) -------
template <int KIN>
__device__ __forceinline__ void buildH2(char* sm, const float* __restrict__ b1, int tid) {
    const float* XS = (const float*)(sm + O_WH);
    const float* W1 = (const float*)(sm + O_WH + 4096);
    __nv_bfloat16* Ah = (__nv_bfloat16*)(sm + O_AH);
    __nv_bfloat16* Al = (__nv_bfloat16*)(sm + O_AL);
    for (int i = tid; i < 4096; i += 256) {
        int row = i >> 6, c = (i & 63) * 2;
        float a0 = __ldg(&b1[c]), a1 = __ldg(&b1[c + 1]);
#pragma unroll
        for (int k = 0; k < KIN; k++) {
            float x = XS[row * KIN + k];
            a0 = fmaf(x, W1[k * 128 + c], a0);
            a1 = fmaf(x, W1[k * 128 + c + 1], a1);
        }
        __nv_bfloat162 hp, lp;
        split_pair(fmaxf(a0, 0.f), fmaxf(a1, 0.f), &hp, &lp);
        *(__nv_bfloat162*)&Ah[row * ASTRIDE + c] = hp;
        *(__nv_bfloat162*)&Al[row * ASTRIDE + c] = lp;
    }
}

template <int KIN>
__device__ __forceinline__ void mlp_side2(char* sm, uint32_t sb,
                                          const float* __restrict__ Xin,
                                          const float* __restrict__ W1,
                                          const float* __restrict__ b1,
                                          int wslot, float (&acc)[8][4],
                                          int tid, int wid, int lane, int row0) {
    const __nv_bfloat16* Ah = (const __nv_bfloat16*)(sm + O_AH);
    const __nv_bfloat16* Al = (const __nv_bfloat16*)(sm + O_AL);
    const __nv_bfloat16* Wh = (const __nv_bfloat16*)(sm + O_WH);
    const __nv_bfloat16* Wl = (const __nv_bfloat16*)(sm + O_WH + 18432);

    // stage XS (64*KIN floats) and W1 (KIN*128 floats) into the WH region
    for (int i = tid; i < 16 * KIN; i += 256)
        ((float4*)(sm + O_WH))[i] = ((const float4*)(Xin + (size_t)row0 * KIN))[i];
    for (int i = tid; i < 32 * KIN; i += 256)
        ((float4*)(sm + O_WH + 4096))[i] = ((const float4*)W1)[i];
    __syncthreads();
    buildH2<KIN>(sm, b1, tid);
    __syncthreads();                 // XS/W1S consumed; WH free for weights

    stage_wt_half(sb + O_WH, wslot, 0, tid);
    CP_COMMIT;
    CP_WAIT(0);
    __syncthreads();
    zero_acc(acc);
    mma_gemm_half(Ah, Al, Wh, Wl, 0, acc, wid, lane);
    __syncthreads();
    stage_wt_half(sb + O_WH, wslot, 1, tid);
    CP_COMMIT;
    CP_WAIT(0);
    __syncthreads();
    mma_gemm_half(Ah, Al, Wh, Wl, 64, acc, wid, lane);
    __syncthreads();
}

// out[row][col] *= (acc + b2)  (RMW)
__device__ __forceinline__ void mul_out(float* __restrict__ outdoc, int row0, const float* __restrict__ b2,
                                        float (&acc)[8][4], int wid, int lane) {
    int m0 = (wid & 3) * 16, n0 = (wid >> 2) * 64;
    int g = lane >> 2, t = lane & 3;
#pragma unroll
    for (int j = 0; j < 8; j++) {
        int row = m0 + g, col = n0 + j * 8 + t * 2;
        float ba = __ldg(&b2[col]), bb = __ldg(&b2[col + 1]);
        float2* p = (float2*)&outdoc[(size_t)(row0 + row) * 128 + col];
        float2 o = *p;
        o.x *= acc[j][0] + ba;
        o.y *= acc[j][1] + bb;
        *p = o;
        p = (float2*)&outdoc[(size_t)(row0 + row + 8) * 128 + col];
        o = *p;
        o.x *= acc[j][2] + ba;
        o.y *= acc[j][3] + bb;
        *p = o;
    }
}

// ------------- merged: layer-2 GEMM (blocks<1024) + feedback/time MLP (rest) -
__global__ void __launch_bounds__(256, 3)
k_gemm2_mlp(const float* __restrict__ bg2, float* __restrict__ out, float* __restrict__ outdoc,
            const float* __restrict__ Xf, const float* __restrict__ Wf1, const float* __restrict__ bf1,
            const float* __restrict__ bf2,
            const float* __restrict__ Xt, const float* __restrict__ Wt1, const float* __restrict__ bt1,
            const float* __restrict__ bt2) {
    extern __shared__ char sm[];
    uint32_t sb = smem_u32(sm);
    int tid = threadIdx.x, wid = tid >> 5, lane = tid & 31;
    if (blockIdx.x < 1024) {
        gemm_tile(g_agg, bg2, out, 2, blockIdx.x * 64, sm, sb, tid, wid, lane);
    } else {
        int row0 = (blockIdx.x - 1024) * 64;
        float acc[8][4];
        mlp_side2<16>(sm, sb, Xf, Wf1, bf1, 3, acc, tid, wid, lane, row0);
        mul_out(outdoc, row0, bf2, acc, wid, lane);
        mlp_side2<8>(sm, sb, Xt, Wt1, bt1, 4, acc, tid, wid, lane, row0);
        mul_out(outdoc, row0, bt2, acc, wid, lane);
    }
}

// ---------------- launch ----------------------------------------------------
extern "C" void kernel_launch(void* const* d_in, const int* in_sizes, int n_in,
                              void* d_out, int out_size) {
    const float* X   = (const float*)d_in[0];
    const float* Xfb = (const float*)d_in[1];
    const float* Xt  = (const float*)d_in[2];
    const int* e_kw2doc = (const int*)d_in[3];
    const float* W0  = (const float*)d_in[6];
    const float* b0  = (const float*)d_in[7];
    const float* Wg1 = (const float*)d_in[8];
    const float* bg1 = (const float*)d_in[9];
    const float* Wg2 = (const float*)d_in[10];
    const float* bg2 = (const float*)d_in[11];
    const float* Wf1 = (const float*)d_in[12];
    const float* bf1 = (const float*)d_in[13];
    const float* Wf2 = (const float*)d_in[14];
    const float* bf2 = (const float*)d_in[15];
    const float* Wt1 = (const float*)d_in[16];
    const float* bt1 = (const float*)d_in[17];
    const float* Wt2 = (const float*)d_in[18];
    const float* bt2 = (const float*)d_in[19];
    float* out = (float*)d_out;
    float* outdoc = out + (size_t)NKW * D;
    const int* src = e_kw2doc;
    const int* dst = e_kw2doc + EDGES;

    cudaFuncSetAttribute(k_fill_gemm0, cudaFuncAttributeMaxDynamicSharedMemorySize, SMEM_GEMM);
    cudaFuncSetAttribute(k_gemm1, cudaFuncAttributeMaxDynamicSharedMemorySize, SMEM_GEMM);
    cudaFuncSetAttribute(k_gemm2_mlp, cudaFuncAttributeMaxDynamicSharedMemorySize, SMEM_GEMM);

    // init counters + weight pre-tiling
    k_prep<<<320, 256>>>(W0, Wg1, Wg2, Wf2, Wt2);

    // merged: layer-0 GEMM (h0, 1024 tiles) + bucket fill (4096 blocks)
    k_fill_gemm0<<<1024 + EDGES / 256, 256, SMEM_GEMM>>>(X, b0, src, dst);

    // layer 1: aggregate h0 kw->doc into g_agg, then docx = relu(g_agg Wg1 + bg1)
    k_gather1<<<NDOC / 8, 256>>>();
    k_gemm1<<<NDOC / 64, 256, SMEM_GEMM>>>(bg1, outdoc);

    // layer 2 aggregation
    k_gather2<<<NKW / 8, 256>>>(outdoc);

    // merged: layer-2 GEMM (kw rows, 1024 tiles) + feedback/time MLP (1024 blocks)
    k_gemm2_mlp<<<2048, 256, SMEM_GEMM>>>(bg2, out, outdoc,
                                          Xfb, Wf1, bf1, bf2, Xt, Wt1, bt1, bt2);
}

// round 16
// speedup vs baseline: 1.2159x; 1.0247x over previous
#include <cuda_runtime.h>
#include <cuda_bf16.h>
#include <cuda_fp16.h>
#include <cstdint>
#include <cstddef>

#define NKW   65536
#define NDOC  65536
#define EDGES 1048576
#define D     128
#define ASTRIDE 136   // bf16 elems per A smem row (272B, conflict-free)
#define WSTRIDE 72    // bf16 elems per W-half smem row (144B, conflict-free)

// ---------------- scratch (device-side only; never referenced from host) ----
__device__ __half g_h0h[(size_t)NKW * D];   // fp16 h0 (gather source + self term)
__device__ __half g_dxh[(size_t)NDOC * D];  // fp16 docx (gather2 source)
__device__ float g_agg[(size_t)NDOC * D];
__device__ int g_cntD[NDOC];
__device__ int g_cntK[NKW];
__device__ int g_bktD[(size_t)NDOC * 64];
__device__ int g_bktK[(size_t)NKW * 64];
// pre-tiled weights: [wslot][khalf][hi/lo][n*64 + kloc]; slots 0=W0 1=Wg1 2=Wg2 3=Wf2 4=Wt2
__device__ __nv_bfloat16 g_wt[5 * 2 * 2 * 8192];

// ---------------- init + weight pre-tiling (one launch) --------------------
__global__ void k_prep(const float* __restrict__ W0, const float* __restrict__ Wg1,
                       const float* __restrict__ Wg2, const float* __restrict__ Wf2,
                       const float* __restrict__ Wt2) {
    int idx = blockIdx.x * blockDim.x + threadIdx.x;
    if (idx < NDOC) g_cntD[idx] = 0;
    if (idx < NKW)  g_cntK[idx] = 0;
    if (idx >= 5 * 16384) return;
    int w = idx >> 14;
    int r = idx & 16383;
    int k = r >> 7, n = r & 127;
    const float* W = (w == 0) ? W0 : (w == 1) ? Wg1 : (w == 2) ? Wg2 : (w == 3) ? Wf2 : Wt2;
    float v = W[k * 128 + n];
    __nv_bfloat16 h = __float2bfloat16(v);
    size_t off = (size_t)w * 32768 + (size_t)(k >> 6) * 16384 + (size_t)n * 64 + (k & 63);
    g_wt[off] = h;
    g_wt[off + 8192] = __float2bfloat16(v - __bfloat162float(h));
}

// ---------------- mma.sync GEMM machinery (M=64 tiles) ----------------------
// smem layout (bytes): A hi 17408 | A lo 17408 | W half hi 18432 | W half lo 18432
#define O_AH 0
#define O_AL 17408
#define O_WH 34816
#define SMEM_GEMM 71680

__device__ __forceinline__ uint32_t smem_u32(const void* p) {
    uint32_t a;
    asm("{ .reg .u64 t; cvta.to.shared.u64 t, %1; cvt.u32.u64 %0, t; }" : "=r"(a) : "l"(p));
    return a;
}

#define CP_COMMIT asm volatile("cp.async.commit_group;" ::: "memory")
#define CP_WAIT(N) asm volatile("cp.async.wait_group %0;" :: "n"(N) : "memory")

__device__ __forceinline__ void cp16(uint32_t dst, const void* src) {
    asm volatile("cp.async.cg.shared.global [%0], [%1], 16;" :: "r"(dst), "l"(src) : "memory");
}

// stream one k-half of a pre-tiled weight (hi+lo, 32KB) into smem at dstb
__device__ __forceinline__ void stage_wt_half(uint32_t dstb, int wslot, int half, int tid) {
    const __nv_bfloat16* base = g_wt + (size_t)wslot * 32768 + (size_t)half * 16384;
#pragma unroll
    for (int it = 0; it < 8; it++) {
        int i = tid + it * 256;
        int hl = i >> 10;
        int idx = i & 1023;
        int n = idx >> 3;
        int c = idx & 7;
        cp16(dstb + hl * 18432 + n * 144 + c * 16, base + hl * 8192 + n * 64 + c * 8);
    }
}

__device__ __forceinline__ void mma16816(float* c, uint32_t a0, uint32_t a1, uint32_t a2, uint32_t a3,
                                         uint32_t b0, uint32_t b1) {
    asm volatile(
        "mma.sync.aligned.m16n8k16.row.col.f32.bf16.bf16.f32 "
        "{%0,%1,%2,%3}, {%4,%5,%6,%7}, {%8,%9}, {%0,%1,%2,%3};"
        : "+f"(c[0]), "+f"(c[1]), "+f"(c[2]), "+f"(c[3])
        : "r"(a0), "r"(a1), "r"(a2), "r"(a3), "r"(b0), "r"(b1));
}

__device__ __forceinline__ void zero_acc(float (&acc)[8][4]) {
#pragma unroll
    for (int j = 0; j < 8; j++)
#pragma unroll
        for (int q = 0; q < 4; q++) acc[j][q] = 0.f;
}

// warp tile: 16 rows x 64 cols; acc += A(:, kk0..kk0+63) * Whalf^T, 3-split bf16.
__device__ __forceinline__ void mma_gemm_half(const __nv_bfloat16* __restrict__ Ah,
                                              const __nv_bfloat16* __restrict__ Al,
                                              const __nv_bfloat16* __restrict__ Bh,
                                              const __nv_bfloat16* __restrict__ Bl,
                                              int kk0, float (&acc)[8][4], int wid, int lane) {
    int m0 = (wid & 3) * 16, n0 = (wid >> 2) * 64;
    int g = lane >> 2, t = lane & 3;
#pragma unroll
    for (int kk = 0; kk < 64; kk += 16) {
        uint32_t ah[4], al[4];
        {
            const __nv_bfloat16* b = &Ah[(m0 + g) * ASTRIDE + kk0 + kk + t * 2];
            ah[0] = *(const uint32_t*)b;
            ah[1] = *(const uint32_t*)(b + 8 * ASTRIDE);
            ah[2] = *(const uint32_t*)(b + 8);
            ah[3] = *(const uint32_t*)(b + 8 * ASTRIDE + 8);
            const __nv_bfloat16* bl2 = &Al[(m0 + g) * ASTRIDE + kk0 + kk + t * 2];
            al[0] = *(const uint32_t*)bl2;
            al[1] = *(const uint32_t*)(bl2 + 8 * ASTRIDE);
            al[2] = *(const uint32_t*)(bl2 + 8);
            al[3] = *(const uint32_t*)(bl2 + 8 * ASTRIDE + 8);
        }
#pragma unroll
        for (int j = 0; j < 8; j++) {
            const __nv_bfloat16* b = &Bh[(n0 + j * 8 + g) * WSTRIDE + kk + t * 2];
            uint32_t bh0 = *(const uint32_t*)b;
            uint32_t bh1 = *(const uint32_t*)(b + 8);
            const __nv_bfloat16* b2 = &Bl[(n0 + j * 8 + g) * WSTRIDE + kk + t * 2];
            uint32_t bl0 = *(const uint32_t*)b2;
            uint32_t bl1 = *(const uint32_t*)(b2 + 8);
            mma16816(acc[j], ah[0], ah[1], ah[2], ah[3], bh0, bh1);
            mma16816(acc[j], ah[0], ah[1], ah[2], ah[3], bl0, bl1);
            mma16816(acc[j], al[0], al[1], al[2], al[3], bh0, bh1);
        }
    }
}

__device__ __forceinline__ void split_pair(float v0, float v1, __nv_bfloat162* hp, __nv_bfloat162* lp) {
    __nv_bfloat16 h0 = __float2bfloat16(v0), h1 = __float2bfloat16(v1);
    hp->x = h0; hp->y = h1;
    lp->x = __float2bfloat16(v0 - __bfloat162float(h0));
    lp->y = __float2bfloat16(v1 - __bfloat162float(h1));
}

// fp32 rows (64) -> bf16 hi/lo A tiles
__device__ __forceinline__ void conv_rows(const float* __restrict__ src, char* sm, int tid) {
    __nv_bfloat16* Ah = (__nv_bfloat16*)(sm + O_AH);
    __nv_bfloat16* Al = (__nv_bfloat16*)(sm + O_AL);
    for (int i = tid; i < 2048; i += 256) {
        int row = i >> 5, c = (i & 31) * 4;
        float4 v = *(const float4*)(src + (size_t)row * 128 + c);
        __nv_bfloat162 hp0, lp0, hp1, lp1;
        split_pair(v.x, v.y, &hp0, &lp0);
        split_pair(v.z, v.w, &hp1, &lp1);
        __nv_bfloat162* ph = (__nv_bfloat162*)&Ah[row * ASTRIDE + c];
        ph[0] = hp0; ph[1] = hp1;
        __nv_bfloat162* pl = (__nv_bfloat162*)&Al[row * ASTRIDE + c];
        pl[0] = lp0; pl[1] = lp1;
    }
}

// epilogue: relu(acc+bias) -> optional fp32 dst and/or fp16 mirror
__device__ __forceinline__ void epi_relu(float* __restrict__ dst, __half* __restrict__ mir,
                                         int row0, const float* __restrict__ bias,
                                         float (&acc)[8][4], int wid, int lane) {
    int m0 = (wid & 3) * 16, n0 = (wid >> 2) * 64;
    int g = lane >> 2, t = lane & 3;
#pragma unroll
    for (int j = 0; j < 8; j++) {
        int row = m0 + g, col = n0 + j * 8 + t * 2;
        float ba = __ldg(&bias[col]), bb = __ldg(&bias[col + 1]);
        float v0 = fmaxf(acc[j][0] + ba, 0.f), v1 = fmaxf(acc[j][1] + bb, 0.f);
        float v2 = fmaxf(acc[j][2] + ba, 0.f), v3 = fmaxf(acc[j][3] + bb, 0.f);
        if (dst) {
            *(float2*)&dst[(size_t)(row0 + row) * 128 + col] = make_float2(v0, v1);
            *(float2*)&dst[(size_t)(row0 + row + 8) * 128 + col] = make_float2(v2, v3);
        }
        if (mir) {
            *(__half2*)&mir[(size_t)(row0 + row) * 128 + col] = __floats2half2_rn(v0, v1);
            *(__half2*)&mir[(size_t)(row0 + row + 8) * 128 + col] = __floats2half2_rn(v2, v3);
        }
    }
}

// full 64x128 GEMM tile
__device__ __forceinline__ void gemm_tile(const float* __restrict__ A, const float* __restrict__ bias,
                                          float* __restrict__ dst, __half* __restrict__ mir,
                                          int wslot, int row0,
                                          char* sm, uint32_t sb, int tid, int wid, int lane) {
    const __nv_bfloat16* Ah = (const __nv_bfloat16*)(sm + O_AH);
    const __nv_bfloat16* Al = (const __nv_bfloat16*)(sm + O_AL);
    const __nv_bfloat16* Wh = (const __nv_bfloat16*)(sm + O_WH);
    const __nv_bfloat16* Wl = (const __nv_bfloat16*)(sm + O_WH + 18432);

    stage_wt_half(sb + O_WH, wslot, 0, tid);
    CP_COMMIT;
    conv_rows(A + (size_t)row0 * 128, sm, tid);
    CP_WAIT(0);
    __syncthreads();

    float acc[8][4];
    zero_acc(acc);
    mma_gemm_half(Ah, Al, Wh, Wl, 0, acc, wid, lane);
    __syncthreads();
    stage_wt_half(sb + O_WH, wslot, 1, tid);
    CP_COMMIT;
    CP_WAIT(0);
    __syncthreads();
    mma_gemm_half(Ah, Al, Wh, Wl, 64, acc, wid, lane);
    epi_relu(dst, mir, row0, bias, acc, wid, lane);
}

// ------------- merged: layer-0 GEMM (blocks<1024) + bucket fill (rest) -------
__global__ void __launch_bounds__(256, 3)
k_fill_gemm0(const float* __restrict__ X, const float* __restrict__ b0,
             const int* __restrict__ src, const int* __restrict__ dst) {
    extern __shared__ char sm[];
    int tid = threadIdx.x;
    if (blockIdx.x < 1024) {
        uint32_t sb = smem_u32(sm);
        gemm_tile(X, b0, nullptr, g_h0h, 0, blockIdx.x * 64, sm, sb, tid, tid >> 5, tid & 31);
    } else {
        int i = (blockIdx.x - 1024) * 256 + tid;   // 4096 blocks cover EDGES
        int s = src[i];
        int dl = dst[i] - NKW;
        int p = atomicAdd(&g_cntD[dl], 1);
        if (p < 64) g_bktD[(size_t)dl * 64 + p] = s;
        int q = atomicAdd(&g_cntK[s], 1);
        if (q < 64) g_bktK[(size_t)s * 64 + q] = dl;
    }
}

// ------------- layer-1 GEMM: outdoc = relu(g_agg Wg1 + bg1), fp16 mirror -----
__global__ void __launch_bounds__(256, 3)
k_gemm1(const float* __restrict__ bias, float* __restrict__ dst) {
    extern __shared__ char sm[];
    uint32_t sb = smem_u32(sm);
    int tid = threadIdx.x;
    gemm_tile(g_agg, bias, dst, g_dxh, 1, blockIdx.x * 64, sm, sb, tid, tid >> 5, tid & 31);
}

// ------------- gathers (fp16 source, unroll 8) --------------------------------
__device__ __forceinline__ void acc_addh(float4& a, uint2 u) {
    float2 f0 = __half22float2(*(__half2*)&u.x);
    float2 f1 = __half22float2(*(__half2*)&u.y);
    a.x += f0.x; a.y += f0.y; a.z += f1.x; a.w += f1.y;
}

__device__ __forceinline__ float4 gather_core(const __half* __restrict__ S,
                                              const int* __restrict__ bkt,
                                              int n, int lane) {
    int m1 = bkt[lane];
    int m2 = bkt[32 + lane];
    float4 a0 = make_float4(0.f, 0.f, 0.f, 0.f), a1 = a0;
    int n1 = n < 32 ? n : 32;
    int e = 0;
    for (; e + 8 <= n1; e += 8) {
        int i0 = __shfl_sync(0xFFFFFFFFu, m1, e);
        int i1 = __shfl_sync(0xFFFFFFFFu, m1, e + 1);
        int i2 = __shfl_sync(0xFFFFFFFFu, m1, e + 2);
        int i3 = __shfl_sync(0xFFFFFFFFu, m1, e + 3);
        int i4 = __shfl_sync(0xFFFFFFFFu, m1, e + 4);
        int i5 = __shfl_sync(0xFFFFFFFFu, m1, e + 5);
        int i6 = __shfl_sync(0xFFFFFFFFu, m1, e + 6);
        int i7 = __shfl_sync(0xFFFFFFFFu, m1, e + 7);
        uint2 v0 = *(const uint2*)&S[(size_t)i0 * D + lane * 4];
        uint2 v1 = *(const uint2*)&S[(size_t)i1 * D + lane * 4];
        uint2 v2 = *(const uint2*)&S[(size_t)i2 * D + lane * 4];
        uint2 v3 = *(const uint2*)&S[(size_t)i3 * D + lane * 4];
        uint2 v4 = *(const uint2*)&S[(size_t)i4 * D + lane * 4];
        uint2 v5 = *(const uint2*)&S[(size_t)i5 * D + lane * 4];
        uint2 v6 = *(const uint2*)&S[(size_t)i6 * D + lane * 4];
        uint2 v7 = *(const uint2*)&S[(size_t)i7 * D + lane * 4];
        acc_addh(a0, v0); acc_addh(a1, v1); acc_addh(a0, v2); acc_addh(a1, v3);
        acc_addh(a0, v4); acc_addh(a1, v5); acc_addh(a0, v6); acc_addh(a1, v7);
    }
    for (; e + 4 <= n1; e += 4) {
        int i0 = __shfl_sync(0xFFFFFFFFu, m1, e);
        int i1 = __shfl_sync(0xFFFFFFFFu, m1, e + 1);
        int i2 = __shfl_sync(0xFFFFFFFFu, m1, e + 2);
        int i3 = __shfl_sync(0xFFFFFFFFu, m1, e + 3);
        uint2 v0 = *(const uint2*)&S[(size_t)i0 * D + lane * 4];
        uint2 v1 = *(const uint2*)&S[(size_t)i1 * D + lane * 4];
        uint2 v2 = *(const uint2*)&S[(size_t)i2 * D + lane * 4];
        uint2 v3 = *(const uint2*)&S[(size_t)i3 * D + lane * 4];
        acc_addh(a0, v0); acc_addh(a1, v1); acc_addh(a0, v2); acc_addh(a1, v3);
    }
    for (; e < n1; e++) {
        int i0 = __shfl_sync(0xFFFFFFFFu, m1, e);
        acc_addh(a0, *(const uint2*)&S[(size_t)i0 * D + lane * 4]);
    }
    for (e = 32; e + 4 <= n; e += 4) {
        int i0 = __shfl_sync(0xFFFFFFFFu, m2, e - 32);
        int i1 = __shfl_sync(0xFFFFFFFFu, m2, e - 31);
        int i2 = __shfl_sync(0xFFFFFFFFu, m2, e - 30);
        int i3 = __shfl_sync(0xFFFFFFFFu, m2, e - 29);
        uint2 v0 = *(const uint2*)&S[(size_t)i0 * D + lane * 4];
        uint2 v1 = *(const uint2*)&S[(size_t)i1 * D + lane * 4];
        uint2 v2 = *(const uint2*)&S[(size_t)i2 * D + lane * 4];
        uint2 v3 = *(const uint2*)&S[(size_t)i3 * D + lane * 4];
        acc_addh(a0, v0); acc_addh(a1, v1); acc_addh(a0, v2); acc_addh(a1, v3);
    }
    for (; e < n; e++) {
        int i0 = __shfl_sync(0xFFFFFFFFu, m2, e - 32);
        acc_addh(a1, *(const uint2*)&S[(size_t)i0 * D + lane * 4]);
    }
    float4 r;
    r.x = a0.x + a1.x; r.y = a0.y + a1.y; r.z = a0.z + a1.z; r.w = a0.w + a1.w;
    return r;
}

__global__ void k_gather1() {
    int w = (blockIdx.x * blockDim.x + threadIdx.x) >> 5;
    int lane = threadIdx.x & 31;
    if (w >= NDOC) return;
    int n = min(g_cntD[w], 64);
    float4 r = gather_core(g_h0h, &g_bktD[(size_t)w * 64], n, lane);
    float s = rsqrtf((float)(n + 1));
    r.x *= s; r.y *= s; r.z *= s; r.w *= s;
    *(float4*)&g_agg[(size_t)w * D + lane * 4] = r;
}

__global__ void k_gather2() {
    int k = (blockIdx.x * blockDim.x + threadIdx.x) >> 5;
    int lane = threadIdx.x & 31;
    if (k >= NKW) return;
    int n = min(g_cntK[k], 64);
    float4 r = gather_core(g_dxh, &g_bktK[(size_t)k * 64], n, lane);
    float deg = (float)(n + 1);
    float s = rsqrtf(deg);
    float inv = 1.f / deg;
    uint2 hu = *(const uint2*)&g_h0h[(size_t)k * D + lane * 4];
    float2 h0 = __half22float2(*(__half2*)&hu.x);
    float2 h1 = __half22float2(*(__half2*)&hu.y);
    r.x = r.x * s + h0.x * inv;
    r.y = r.y * s + h0.y * inv;
    r.z = r.z * s + h1.x * inv;
    r.w = r.w * s + h1.y * inv;
    *(float4*)&g_agg[(size_t)k * D + lane * 4] = r;
}

// ------------- MLP pieces (M=64 tiles; XS/W1S overlaid into WH region) -------
template <int KIN>
__device__ __forceinline__ void buildH2(char* sm, const float* __restrict__ b1, int tid) {
    const float* XS = (const float*)(sm + O_WH);
    const float* W1 = (const float*)(sm + O_WH + 4096);
    __nv_bfloat16* Ah = (__nv_bfloat16*)(sm + O_AH);
    __nv_bfloat16* Al = (__nv_bfloat16*)(sm + O_AL);
    for (int i = tid; i < 4096; i += 256) {
        int row = i >> 6, c = (i & 63) * 2;
        float a0 = __ldg(&b1[c]), a1 = __ldg(&b1[c + 1]);
#pragma unroll
        for (int k = 0; k < KIN; k++) {
            float x = XS[row * KIN + k];
            a0 = fmaf(x, W1[k * 128 + c], a0);
            a1 = fmaf(x, W1[k * 128 + c + 1], a1);
        }
        __nv_bfloat162 hp, lp;
        split_pair(fmaxf(a0, 0.f), fmaxf(a1, 0.f), &hp, &lp);
        *(__nv_bfloat162*)&Ah[row * ASTRIDE + c] = hp;
        *(__nv_bfloat162*)&Al[row * ASTRIDE + c] = lp;
    }
}

template <int KIN>
__device__ __forceinline__ void mlp_side2(char* sm, uint32_t sb,
                                          const float* __restrict__ Xin,
                                          const float* __restrict__ W1,
                                          const float* __restrict__ b1,
                                          int wslot, float (&acc)[8][4],
                                          int tid, int wid, int lane, int row0) {
    const __nv_bfloat16* Ah = (const __nv_bfloat16*)(sm + O_AH);
    const __nv_bfloat16* Al = (const __nv_bfloat16*)(sm + O_AL);
    const __nv_bfloat16* Wh = (const __nv_bfloat16*)(sm + O_WH);
    const __nv_bfloat16* Wl = (const __nv_bfloat16*)(sm + O_WH + 18432);

    for (int i = tid; i < 16 * KIN; i += 256)
        ((float4*)(sm + O_WH))[i] = ((const float4*)(Xin + (size_t)row0 * KIN))[i];
    for (int i = tid; i < 32 * KIN; i += 256)
        ((float4*)(sm + O_WH + 4096))[i] = ((const float4*)W1)[i];
    __syncthreads();
    buildH2<KIN>(sm, b1, tid);
    __syncthreads();

    stage_wt_half(sb + O_WH, wslot, 0, tid);
    CP_COMMIT;
    CP_WAIT(0);
    __syncthreads();
    zero_acc(acc);
    mma_gemm_half(Ah, Al, Wh, Wl, 0, acc, wid, lane);
    __syncthreads();
    stage_wt_half(sb + O_WH, wslot, 1, tid);
    CP_COMMIT;
    CP_WAIT(0);
    __syncthreads();
    mma_gemm_half(Ah, Al, Wh, Wl, 64, acc, wid, lane);
    __syncthreads();
}

// out[row][col] *= (acc + b2)  (RMW)
__device__ __forceinline__ void mul_out(float* __restrict__ outdoc, int row0, const float* __restrict__ b2,
                                        float (&acc)[8][4], int wid, int lane) {
    int m0 = (wid & 3) * 16, n0 = (wid >> 2) * 64;
    int g = lane >> 2, t = lane & 3;
#pragma unroll
    for (int j = 0; j < 8; j++) {
        int row = m0 + g, col = n0 + j * 8 + t * 2;
        float ba = __ldg(&b2[col]), bb = __ldg(&b2[col + 1]);
        float2* p = (float2*)&outdoc[(size_t)(row0 + row) * 128 + col];
        float2 o = *p;
        o.x *= acc[j][0] + ba;
        o.y *= acc[j][1] + bb;
        *p = o;
        p = (float2*)&outdoc[(size_t)(row0 + row + 8) * 128 + col];
        o = *p;
        o.x *= acc[j][2] + ba;
        o.y *= acc[j][3] + bb;
        *p = o;
    }
}

// ------------- merged: layer-2 GEMM (blocks<1024) + feedback/time MLP (rest) -
__global__ void __launch_bounds__(256, 3)
k_gemm2_mlp(const float* __restrict__ bg2, float* __restrict__ out, float* __restrict__ outdoc,
            const float* __restrict__ Xf, const float* __restrict__ Wf1, const float* __restrict__ bf1,
            const float* __restrict__ bf2,
            const float* __restrict__ Xt, const float* __restrict__ Wt1, const float* __restrict__ bt1,
            const float* __restrict__ bt2) {
    extern __shared__ char sm[];
    uint32_t sb = smem_u32(sm);
    int tid = threadIdx.x, wid = tid >> 5, lane = tid & 31;
    if (blockIdx.x < 1024) {
        gemm_tile(g_agg, bg2, out, nullptr, 2, blockIdx.x * 64, sm, sb, tid, wid, lane);
    } else {
        int row0 = (blockIdx.x - 1024) * 64;
        float acc[8][4];
        mlp_side2<16>(sm, sb, Xf, Wf1, bf1, 3, acc, tid, wid, lane, row0);
        mul_out(outdoc, row0, bf2, acc, wid, lane);
        mlp_side2<8>(sm, sb, Xt, Wt1, bt1, 4, acc, tid, wid, lane, row0);
        mul_out(outdoc, row0, bt2, acc, wid, lane);
    }
}

// ---------------- launch ----------------------------------------------------
extern "C" void kernel_launch(void* const* d_in, const int* in_sizes, int n_in,
                              void* d_out, int out_size) {
    const float* X   = (const float*)d_in[0];
    const float* Xfb = (const float*)d_in[1];
    const float* Xt  = (const float*)d_in[2];
    const int* e_kw2doc = (const int*)d_in[3];
    const float* W0  = (const float*)d_in[6];
    const float* b0  = (const float*)d_in[7];
    const float* Wg1 = (const float*)d_in[8];
    const float* bg1 = (const float*)d_in[9];
    const float* Wg2 = (const float*)d_in[10];
    const float* bg2 = (const float*)d_in[11];
    const float* Wf1 = (const float*)d_in[12];
    const float* bf1 = (const float*)d_in[13];
    const float* Wf2 = (const float*)d_in[14];
    const float* bf2 = (const float*)d_in[15];
    const float* Wt1 = (const float*)d_in[16];
    const float* bt1 = (const float*)d_in[17];
    const float* Wt2 = (const float*)d_in[18];
    const float* bt2 = (const float*)d_in[19];
    float* out = (float*)d_out;
    float* outdoc = out + (size_t)NKW * D;
    const int* src = e_kw2doc;
    const int* dst = e_kw2doc + EDGES;

    cudaFuncSetAttribute(k_fill_gemm0, cudaFuncAttributeMaxDynamicSharedMemorySize, SMEM_GEMM);
    cudaFuncSetAttribute(k_gemm1, cudaFuncAttributeMaxDynamicSharedMemorySize, SMEM_GEMM);
    cudaFuncSetAttribute(k_gemm2_mlp, cudaFuncAttributeMaxDynamicSharedMemorySize, SMEM_GEMM);

    // init counters + weight pre-tiling
    k_prep<<<320, 256>>>(W0, Wg1, Wg2, Wf2, Wt2);

    // merged: layer-0 GEMM (h0 -> fp16) + bucket fill
    k_fill_gemm0<<<1024 + EDGES / 256, 256, SMEM_GEMM>>>(X, b0, src, dst);

    // layer 1: fp16 gather kw->doc into g_agg, then docx = relu(g_agg Wg1 + bg1) (+fp16 mirror)
    k_gather1<<<NDOC / 8, 256>>>();
    k_gemm1<<<NDOC / 64, 256, SMEM_GEMM>>>(bg1, outdoc);

    // layer 2: fp16 gather doc->kw (+ fp16 self term) into g_agg
    k_gather2<<<NKW / 8, 256>>>();

    // merged: layer-2 GEMM (kw rows) + feedback/time MLP (doc rows RMW)
    k_gemm2_mlp<<<2048, 256, SMEM_GEMM>>>(bg2, out, outdoc,
                                          Xfb, Wf1, bf1, bf2, Xt, Wt1, bt1, bt2);
}

// round 17
// speedup vs baseline: 1.3287x; 1.0928x over previous
#include <cuda_runtime.h>
#include <cuda_fp16.h>
#include <cstdint>
#include <cstddef>

#define NKW   65536
#define NDOC  65536
#define EDGES 1048576
#define D     128
#define ASTRIDE 136   // fp16 elems per A smem row (272B, conflict-free)
#define WSTRIDE 72    // fp16 elems per W-half smem row (144B, conflict-free)

// ---------------- scratch (device-side only; never referenced from host) ----
__device__ __half g_h0h[(size_t)NKW * D];   // fp16 h0
__device__ __half g_dxh[(size_t)NDOC * D];  // fp16 docx
__device__ __half g_aggh[(size_t)NDOC * D]; // fp16 aggregation output
__device__ int g_cntD[NDOC];
__device__ int g_cntK[NKW];
__device__ int g_bktD[(size_t)NDOC * 64];
__device__ int g_bktK[(size_t)NKW * 64];
// pre-tiled weights fp16 hi/lo: [wslot][khalf][hi/lo][n*64 + kloc]; 0=W0 1=Wg1 2=Wg2 3=Wf2 4=Wt2
__device__ __half g_wt[5 * 2 * 2 * 8192];

// ---------------- init + weight pre-tiling (one launch) --------------------
__global__ void k_prep(const float* __restrict__ W0, const float* __restrict__ Wg1,
                       const float* __restrict__ Wg2, const float* __restrict__ Wf2,
                       const float* __restrict__ Wt2) {
    int idx = blockIdx.x * blockDim.x + threadIdx.x;
    if (idx < NDOC) g_cntD[idx] = 0;
    if (idx < NKW)  g_cntK[idx] = 0;
    if (idx >= 5 * 16384) return;
    int w = idx >> 14;
    int r = idx & 16383;
    int k = r >> 7, n = r & 127;
    const float* W = (w == 0) ? W0 : (w == 1) ? Wg1 : (w == 2) ? Wg2 : (w == 3) ? Wf2 : Wt2;
    float v = W[k * 128 + n];
    __half h = __float2half_rn(v);
    size_t off = (size_t)w * 32768 + (size_t)(k >> 6) * 16384 + (size_t)n * 64 + (k & 63);
    g_wt[off] = h;
    g_wt[off + 8192] = __float2half_rn(v - __half2float(h));
}

// ---------------- mma.sync GEMM machinery (M=64 tiles, fp16 A single) -------
// smem layout (bytes): A 17408 | W half hi 18432 | W half lo 18432
#define O_A  0
#define O_WH 17408
#define SMEM_GEMM 54272

__device__ __forceinline__ uint32_t smem_u32(const void* p) {
    uint32_t a;
    asm("{ .reg .u64 t; cvta.to.shared.u64 t, %1; cvt.u32.u64 %0, t; }" : "=r"(a) : "l"(p));
    return a;
}

#define CP_COMMIT asm volatile("cp.async.commit_group;" ::: "memory")
#define CP_WAIT(N) asm volatile("cp.async.wait_group %0;" :: "n"(N) : "memory")

__device__ __forceinline__ void cp16(uint32_t dst, const void* src) {
    asm volatile("cp.async.cg.shared.global [%0], [%1], 16;" :: "r"(dst), "l"(src) : "memory");
}

// stream one k-half of a pre-tiled weight (hi+lo, 32KB) into smem at dstb
__device__ __forceinline__ void stage_wt_half(uint32_t dstb, int wslot, int half, int tid) {
    const __half* base = g_wt + (size_t)wslot * 32768 + (size_t)half * 16384;
#pragma unroll
    for (int it = 0; it < 8; it++) {
        int i = tid + it * 256;
        int hl = i >> 10;
        int idx = i & 1023;
        int n = idx >> 3;
        int c = idx & 7;
        cp16(dstb + hl * 18432 + n * 144 + c * 16, base + hl * 8192 + n * 64 + c * 8);
    }
}

// stage fp16 A tile (64 rows x 128) straight from gmem via cp.async
__device__ __forceinline__ void stage_A_h(uint32_t sb, const __half* __restrict__ S, int row0, int tid) {
#pragma unroll
    for (int it = 0; it < 4; it++) {
        int i = tid + it * 256;
        int row = i >> 4, c = i & 15;
        cp16(sb + O_A + row * 272 + c * 16, S + (size_t)(row0 + row) * 128 + c * 8);
    }
}

__device__ __forceinline__ void mma16816(float* c, uint32_t a0, uint32_t a1, uint32_t a2, uint32_t a3,
                                         uint32_t b0, uint32_t b1) {
    asm volatile(
        "mma.sync.aligned.m16n8k16.row.col.f32.f16.f16.f32 "
        "{%0,%1,%2,%3}, {%4,%5,%6,%7}, {%8,%9}, {%0,%1,%2,%3};"
        : "+f"(c[0]), "+f"(c[1]), "+f"(c[2]), "+f"(c[3])
        : "r"(a0), "r"(a1), "r"(a2), "r"(a3), "r"(b0), "r"(b1));
}

__device__ __forceinline__ void zero_acc(float (&acc)[8][4]) {
#pragma unroll
    for (int j = 0; j < 8; j++)
#pragma unroll
        for (int q = 0; q < 4; q++) acc[j][q] = 0.f;
}

// warp tile: 16 rows x 64 cols; acc += A(:, kk0..kk0+63) * Whalf^T, 2-split fp16.
__device__ __forceinline__ void mma_gemm_half(const __half* __restrict__ Ah,
                                              const __half* __restrict__ Bh,
                                              const __half* __restrict__ Bl,
                                              int kk0, float (&acc)[8][4], int wid, int lane) {
    int m0 = (wid & 3) * 16, n0 = (wid >> 2) * 64;
    int g = lane >> 2, t = lane & 3;
#pragma unroll
    for (int kk = 0; kk < 64; kk += 16) {
        uint32_t ah[4];
        {
            const __half* b = &Ah[(m0 + g) * ASTRIDE + kk0 + kk + t * 2];
            ah[0] = *(const uint32_t*)b;
            ah[1] = *(const uint32_t*)(b + 8 * ASTRIDE);
            ah[2] = *(const uint32_t*)(b + 8);
            ah[3] = *(const uint32_t*)(b + 8 * ASTRIDE + 8);
        }
#pragma unroll
        for (int j = 0; j < 8; j++) {
            const __half* b = &Bh[(n0 + j * 8 + g) * WSTRIDE + kk + t * 2];
            uint32_t bh0 = *(const uint32_t*)b;
            uint32_t bh1 = *(const uint32_t*)(b + 8);
            const __half* b2 = &Bl[(n0 + j * 8 + g) * WSTRIDE + kk + t * 2];
            uint32_t bl0 = *(const uint32_t*)b2;
            uint32_t bl1 = *(const uint32_t*)(b2 + 8);
            mma16816(acc[j], ah[0], ah[1], ah[2], ah[3], bh0, bh1);
            mma16816(acc[j], ah[0], ah[1], ah[2], ah[3], bl0, bl1);
        }
    }
}

// fp32 rows (64) -> fp16 A tile (for layer-0 X input)
__device__ __forceinline__ void conv_rows_f32(const float* __restrict__ src, char* sm, int tid) {
    __half* Ah = (__half*)(sm + O_A);
    for (int i = tid; i < 2048; i += 256) {
        int row = i >> 5, c = (i & 31) * 4;
        float4 v = *(const float4*)(src + (size_t)row * 128 + c);
        *(__half2*)&Ah[row * ASTRIDE + c] = __floats2half2_rn(v.x, v.y);
        *(__half2*)&Ah[row * ASTRIDE + c + 2] = __floats2half2_rn(v.z, v.w);
    }
}

// epilogue: relu(acc+bias) -> optional fp32 dst and/or fp16 mirror
__device__ __forceinline__ void epi_relu(float* __restrict__ dst, __half* __restrict__ mir,
                                         int row0, const float* __restrict__ bias,
                                         float (&acc)[8][4], int wid, int lane) {
    int m0 = (wid & 3) * 16, n0 = (wid >> 2) * 64;
    int g = lane >> 2, t = lane & 3;
#pragma unroll
    for (int j = 0; j < 8; j++) {
        int row = m0 + g, col = n0 + j * 8 + t * 2;
        float ba = __ldg(&bias[col]), bb = __ldg(&bias[col + 1]);
        float v0 = fmaxf(acc[j][0] + ba, 0.f), v1 = fmaxf(acc[j][1] + bb, 0.f);
        float v2 = fmaxf(acc[j][2] + ba, 0.f), v3 = fmaxf(acc[j][3] + bb, 0.f);
        if (dst) {
            *(float2*)&dst[(size_t)(row0 + row) * 128 + col] = make_float2(v0, v1);
            *(float2*)&dst[(size_t)(row0 + row + 8) * 128 + col] = make_float2(v2, v3);
        }
        if (mir) {
            *(__half2*)&mir[(size_t)(row0 + row) * 128 + col] = __floats2half2_rn(v0, v1);
            *(__half2*)&mir[(size_t)(row0 + row + 8) * 128 + col] = __floats2half2_rn(v2, v3);
        }
    }
}

// GEMM tile core (after A is staged): 64x128
__device__ __forceinline__ void gemm_core(float* __restrict__ dst, __half* __restrict__ mir,
                                          const float* __restrict__ bias, int wslot, int row0,
                                          char* sm, uint32_t sb, int tid, int wid, int lane) {
    const __half* Ah = (const __half*)(sm + O_A);
    const __half* Wh = (const __half*)(sm + O_WH);
    const __half* Wl = (const __half*)(sm + O_WH + 18432);
    float acc[8][4];
    zero_acc(acc);
    mma_gemm_half(Ah, Wh, Wl, 0, acc, wid, lane);
    __syncthreads();
    stage_wt_half(sb + O_WH, wslot, 1, tid);
    CP_COMMIT;
    CP_WAIT(0);
    __syncthreads();
    mma_gemm_half(Ah, Wh, Wl, 64, acc, wid, lane);
    epi_relu(dst, mir, row0, bias, acc, wid, lane);
}

// ------------- merged: layer-0 GEMM (blocks<1024) + bucket fill (rest) -------
__global__ void __launch_bounds__(256, 4)
k_fill_gemm0(const float* __restrict__ X, const float* __restrict__ b0,
             const int* __restrict__ src, const int* __restrict__ dst) {
    extern __shared__ char sm[];
    int tid = threadIdx.x;
    if (blockIdx.x < 1024) {
        uint32_t sb = smem_u32(sm);
        int row0 = blockIdx.x * 64;
        stage_wt_half(sb + O_WH, 0, 0, tid);
        CP_COMMIT;
        conv_rows_f32(X + (size_t)row0 * 128, sm, tid);
        CP_WAIT(0);
        __syncthreads();
        gemm_core(nullptr, g_h0h, b0, 0, row0, sm, sb, tid, tid >> 5, tid & 31);
    } else {
        int i = (blockIdx.x - 1024) * 256 + tid;   // 4096 blocks cover EDGES
        int s = src[i];
        int dl = dst[i] - NKW;
        int p = atomicAdd(&g_cntD[dl], 1);
        if (p < 64) g_bktD[(size_t)dl * 64 + p] = s;
        int q = atomicAdd(&g_cntK[s], 1);
        if (q < 64) g_bktK[(size_t)s * 64 + q] = dl;
    }
}

// ------------- layer-1 GEMM: outdoc = relu(g_aggh Wg1 + bg1), fp16 mirror ----
__global__ void __launch_bounds__(256, 4)
k_gemm1(const float* __restrict__ bias, float* __restrict__ dst) {
    extern __shared__ char sm[];
    uint32_t sb = smem_u32(sm);
    int tid = threadIdx.x;
    int row0 = blockIdx.x * 64;
    stage_wt_half(sb + O_WH, 1, 0, tid);
    stage_A_h(sb, g_aggh, row0, tid);
    CP_COMMIT;
    CP_WAIT(0);
    __syncthreads();
    gemm_core(dst, g_dxh, bias, 1, row0, sm, sb, tid, tid >> 5, tid & 31);
}

// ------------- gathers (fp16 source, fp16 dest, unroll 8) --------------------
__device__ __forceinline__ void acc_addh(float4& a, uint2 u) {
    float2 f0 = __half22float2(*(__half2*)&u.x);
    float2 f1 = __half22float2(*(__half2*)&u.y);
    a.x += f0.x; a.y += f0.y; a.z += f1.x; a.w += f1.y;
}

__device__ __forceinline__ float4 gather_core(const __half* __restrict__ S,
                                              const int* __restrict__ bkt,
                                              int n, int lane) {
    int m1 = bkt[lane];
    int m2 = bkt[32 + lane];
    float4 a0 = make_float4(0.f, 0.f, 0.f, 0.f), a1 = a0;
    int n1 = n < 32 ? n : 32;
    int e = 0;
    for (; e + 8 <= n1; e += 8) {
        int i0 = __shfl_sync(0xFFFFFFFFu, m1, e);
        int i1 = __shfl_sync(0xFFFFFFFFu, m1, e + 1);
        int i2 = __shfl_sync(0xFFFFFFFFu, m1, e + 2);
        int i3 = __shfl_sync(0xFFFFFFFFu, m1, e + 3);
        int i4 = __shfl_sync(0xFFFFFFFFu, m1, e + 4);
        int i5 = __shfl_sync(0xFFFFFFFFu, m1, e + 5);
        int i6 = __shfl_sync(0xFFFFFFFFu, m1, e + 6);
        int i7 = __shfl_sync(0xFFFFFFFFu, m1, e + 7);
        uint2 v0 = *(const uint2*)&S[(size_t)i0 * D + lane * 4];
        uint2 v1 = *(const uint2*)&S[(size_t)i1 * D + lane * 4];
        uint2 v2 = *(const uint2*)&S[(size_t)i2 * D + lane * 4];
        uint2 v3 = *(const uint2*)&S[(size_t)i3 * D + lane * 4];
        uint2 v4 = *(const uint2*)&S[(size_t)i4 * D + lane * 4];
        uint2 v5 = *(const uint2*)&S[(size_t)i5 * D + lane * 4];
        uint2 v6 = *(const uint2*)&S[(size_t)i6 * D + lane * 4];
        uint2 v7 = *(const uint2*)&S[(size_t)i7 * D + lane * 4];
        acc_addh(a0, v0); acc_addh(a1, v1); acc_addh(a0, v2); acc_addh(a1, v3);
        acc_addh(a0, v4); acc_addh(a1, v5); acc_addh(a0, v6); acc_addh(a1, v7);
    }
    for (; e + 4 <= n1; e += 4) {
        int i0 = __shfl_sync(0xFFFFFFFFu, m1, e);
        int i1 = __shfl_sync(0xFFFFFFFFu, m1, e + 1);
        int i2 = __shfl_sync(0xFFFFFFFFu, m1, e + 2);
        int i3 = __shfl_sync(0xFFFFFFFFu, m1, e + 3);
        uint2 v0 = *(const uint2*)&S[(size_t)i0 * D + lane * 4];
        uint2 v1 = *(const uint2*)&S[(size_t)i1 * D + lane * 4];
        uint2 v2 = *(const uint2*)&S[(size_t)i2 * D + lane * 4];
        uint2 v3 = *(const uint2*)&S[(size_t)i3 * D + lane * 4];
        acc_addh(a0, v0); acc_addh(a1, v1); acc_addh(a0, v2); acc_addh(a1, v3);
    }
    for (; e < n1; e++) {
        int i0 = __shfl_sync(0xFFFFFFFFu, m1, e);
        acc_addh(a0, *(const uint2*)&S[(size_t)i0 * D + lane * 4]);
    }
    for (e = 32; e + 4 <= n; e += 4) {
        int i0 = __shfl_sync(0xFFFFFFFFu, m2, e - 32);
        int i1 = __shfl_sync(0xFFFFFFFFu, m2, e - 31);
        int i2 = __shfl_sync(0xFFFFFFFFu, m2, e - 30);
        int i3 = __shfl_sync(0xFFFFFFFFu, m2, e - 29);
        uint2 v0 = *(const uint2*)&S[(size_t)i0 * D + lane * 4];
        uint2 v1 = *(const uint2*)&S[(size_t)i1 * D + lane * 4];
        uint2 v2 = *(const uint2*)&S[(size_t)i2 * D + lane * 4];
        uint2 v3 = *(const uint2*)&S[(size_t)i3 * D + lane * 4];
        acc_addh(a0, v0); acc_addh(a1, v1); acc_addh(a0, v2); acc_addh(a1, v3);
    }
    for (; e < n; e++) {
        int i0 = __shfl_sync(0xFFFFFFFFu, m2, e - 32);
        acc_addh(a1, *(const uint2*)&S[(size_t)i0 * D + lane * 4]);
    }
    float4 r;
    r.x = a0.x + a1.x; r.y = a0.y + a1.y; r.z = a0.z + a1.z; r.w = a0.w + a1.w;
    return r;
}

__device__ __forceinline__ void store_h4(__half* p, float4 r) {
    uint2 u;
    *(__half2*)&u.x = __floats2half2_rn(r.x, r.y);
    *(__half2*)&u.y = __floats2half2_rn(r.z, r.w);
    *(uint2*)p = u;
}

__global__ void k_gather1() {
    int w = (blockIdx.x * blockDim.x + threadIdx.x) >> 5;
    int lane = threadIdx.x & 31;
    if (w >= NDOC) return;
    int n = min(g_cntD[w], 64);
    float4 r = gather_core(g_h0h, &g_bktD[(size_t)w * 64], n, lane);
    float s = rsqrtf((float)(n + 1));
    r.x *= s; r.y *= s; r.z *= s; r.w *= s;
    store_h4(&g_aggh[(size_t)w * D + lane * 4], r);
}

__global__ void k_gather2() {
    int k = (blockIdx.x * blockDim.x + threadIdx.x) >> 5;
    int lane = threadIdx.x & 31;
    if (k >= NKW) return;
    int n = min(g_cntK[k], 64);
    float4 r = gather_core(g_dxh, &g_bktK[(size_t)k * 64], n, lane);
    float deg = (float)(n + 1);
    float s = rsqrtf(deg);
    float inv = 1.f / deg;
    uint2 hu = *(const uint2*)&g_h0h[(size_t)k * D + lane * 4];
    float2 h0 = __half22float2(*(__half2*)&hu.x);
    float2 h1 = __half22float2(*(__half2*)&hu.y);
    r.x = r.x * s + h0.x * inv;
    r.y = r.y * s + h0.y * inv;
    r.z = r.z * s + h1.x * inv;
    r.w = r.w * s + h1.y * inv;
    store_h4(&g_aggh[(size_t)k * D + lane * 4], r);
}

// ------------- MLP pieces (fp16 A; XS/W1S overlaid into WH region) -----------
template <int KIN>
__device__ __forceinline__ void buildH2(char* sm, const float* __restrict__ b1, int tid) {
    const float* XS = (const float*)(sm + O_WH);
    const float* W1 = (const float*)(sm + O_WH + 4096);
    __half* Ah = (__half*)(sm + O_A);
    for (int i = tid; i < 4096; i += 256) {
        int row = i >> 6, c = (i & 63) * 2;
        float a0 = __ldg(&b1[c]), a1 = __ldg(&b1[c + 1]);
#pragma unroll
        for (int k = 0; k < KIN; k++) {
            float x = XS[row * KIN + k];
            a0 = fmaf(x, W1[k * 128 + c], a0);
            a1 = fmaf(x, W1[k * 128 + c + 1], a1);
        }
        *(__half2*)&Ah[row * ASTRIDE + c] = __floats2half2_rn(fmaxf(a0, 0.f), fmaxf(a1, 0.f));
    }
}

template <int KIN>
__device__ __forceinline__ void mlp_side2(char* sm, uint32_t sb,
                                          const float* __restrict__ Xin,
                                          const float* __restrict__ W1,
                                          const float* __restrict__ b1,
                                          int wslot, float (&acc)[8][4],
                                          int tid, int wid, int lane, int row0) {
    const __half* Ah = (const __half*)(sm + O_A);
    const __half* Wh = (const __half*)(sm + O_WH);
    const __half* Wl = (const __half*)(sm + O_WH + 18432);

    for (int i = tid; i < 16 * KIN; i += 256)
        ((float4*)(sm + O_WH))[i] = ((const float4*)(Xin + (size_t)row0 * KIN))[i];
    for (int i = tid; i < 32 * KIN; i += 256)
        ((float4*)(sm + O_WH + 4096))[i] = ((const float4*)W1)[i];
    __syncthreads();
    buildH2<KIN>(sm, b1, tid);
    __syncthreads();

    stage_wt_half(sb + O_WH, wslot, 0, tid);
    CP_COMMIT;
    CP_WAIT(0);
    __syncthreads();
    zero_acc(acc);
    mma_gemm_half(Ah, Wh, Wl, 0, acc, wid, lane);
    __syncthreads();
    stage_wt_half(sb + O_WH, wslot, 1, tid);
    CP_COMMIT;
    CP_WAIT(0);
    __syncthreads();
    mma_gemm_half(Ah, Wh, Wl, 64, acc, wid, lane);
    __syncthreads();
}

// out[row][col] *= (acc + b2)  (RMW)
__device__ __forceinline__ void mul_out(float* __restrict__ outdoc, int row0, const float* __restrict__ b2,
                                        float (&acc)[8][4], int wid, int lane) {
    int m0 = (wid & 3) * 16, n0 = (wid >> 2) * 64;
    int g = lane >> 2, t = lane & 3;
#pragma unroll
    for (int j = 0; j < 8; j++) {
        int row = m0 + g, col = n0 + j * 8 + t * 2;
        float ba = __ldg(&b2[col]), bb = __ldg(&b2[col + 1]);
        float2* p = (float2*)&outdoc[(size_t)(row0 + row) * 128 + col];
        float2 o = *p;
        o.x *= acc[j][0] + ba;
        o.y *= acc[j][1] + bb;
        *p = o;
        p = (float2*)&outdoc[(size_t)(row0 + row + 8) * 128 + col];
        o = *p;
        o.x *= acc[j][2] + ba;
        o.y *= acc[j][3] + bb;
        *p = o;
    }
}

// ------------- merged: layer-2 GEMM (blocks<1024) + feedback/time MLP (rest) -
__global__ void __launch_bounds__(256, 4)
k_gemm2_mlp(const float* __restrict__ bg2, float* __restrict__ out, float* __restrict__ outdoc,
            const float* __restrict__ Xf, const float* __restrict__ Wf1, const float* __restrict__ bf1,
            const float* __restrict__ bf2,
            const float* __restrict__ Xt, const float* __restrict__ Wt1, const float* __restrict__ bt1,
            const float* __restrict__ bt2) {
    extern __shared__ char sm[];
    uint32_t sb = smem_u32(sm);
    int tid = threadIdx.x, wid = tid >> 5, lane = tid & 31;
    if (blockIdx.x < 1024) {
        int row0 = blockIdx.x * 64;
        stage_wt_half(sb + O_WH, 2, 0, tid);
        stage_A_h(sb, g_aggh, row0, tid);
        CP_COMMIT;
        CP_WAIT(0);
        __syncthreads();
        gemm_core(out, nullptr, bg2, 2, row0, sm, sb, tid, wid, lane);
    } else {
        int row0 = (blockIdx.x - 1024) * 64;
        float acc[8][4];
        mlp_side2<16>(sm, sb, Xf, Wf1, bf1, 3, acc, tid, wid, lane, row0);
        mul_out(outdoc, row0, bf2, acc, wid, lane);
        mlp_side2<8>(sm, sb, Xt, Wt1, bt1, 4, acc, tid, wid, lane, row0);
        mul_out(outdoc, row0, bt2, acc, wid, lane);
    }
}

// ---------------- launch ----------------------------------------------------
extern "C" void kernel_launch(void* const* d_in, const int* in_sizes, int n_in,
                              void* d_out, int out_size) {
    const float* X   = (const float*)d_in[0];
    const float* Xfb = (const float*)d_in[1];
    const float* Xt  = (const float*)d_in[2];
    const int* e_kw2doc = (const int*)d_in[3];
    const float* W0  = (const float*)d_in[6];
    const float* b0  = (const float*)d_in[7];
    const float* Wg1 = (const float*)d_in[8];
    const float* bg1 = (const float*)d_in[9];
    const float* Wg2 = (const float*)d_in[10];
    const float* bg2 = (const float*)d_in[11];
    const float* Wf1 = (const float*)d_in[12];
    const float* bf1 = (const float*)d_in[13];
    const float* Wf2 = (const float*)d_in[14];
    const float* bf2 = (const float*)d_in[15];
    const float* Wt1 = (const float*)d_in[16];
    const float* bt1 = (const float*)d_in[17];
    const float* Wt2 = (const float*)d_in[18];
    const float* bt2 = (const float*)d_in[19];
    float* out = (float*)d_out;
    float* outdoc = out + (size_t)NKW * D;
    const int* src = e_kw2doc;
    const int* dst = e_kw2doc + EDGES;

    cudaFuncSetAttribute(k_fill_gemm0, cudaFuncAttributeMaxDynamicSharedMemorySize, SMEM_GEMM);
    cudaFuncSetAttribute(k_gemm1, cudaFuncAttributeMaxDynamicSharedMemorySize, SMEM_GEMM);
    cudaFuncSetAttribute(k_gemm2_mlp, cudaFuncAttributeMaxDynamicSharedMemorySize, SMEM_GEMM);

    // init counters + weight pre-tiling (fp16 hi/lo)
    k_prep<<<320, 256>>>(W0, Wg1, Wg2, Wf2, Wt2);

    // merged: layer-0 GEMM (X fp32 -> h0 fp16) + bucket fill
    k_fill_gemm0<<<1024 + EDGES / 256, 256, SMEM_GEMM>>>(X, b0, src, dst);

    // layer 1: fp16 gather kw->doc into g_aggh, then docx = relu(g_aggh Wg1 + bg1)
    k_gather1<<<NDOC / 8, 256>>>();
    k_gemm1<<<NDOC / 64, 256, SMEM_GEMM>>>(bg1, outdoc);

    // layer 2: fp16 gather doc->kw (+ fp16 self term) into g_aggh
    k_gather2<<<NKW / 8, 256>>>();

    // merged: layer-2 GEMM (kw rows) + feedback/time MLP (doc rows RMW)
    k_gemm2_mlp<<<2048, 256, SMEM_GEMM>>>(bg2, out, outdoc,
                                          Xfb, Wf1, bf1, bf2, Xt, Wt1, bt1, bt2);
}